// round 9
// baseline (speedup 1.0000x reference)
#include <cuda_runtime.h>
#include <cuda_bf16.h>
#include <cstdint>

#define N_NODESC 8192
#define N_EDGESC 262144
#define D_FEATC  512
#define NHIDC    32
#define LATENTC  16

// output layout (float elements)
#define ADJ_OFF  0ull
#define FEAT_OFF 67108864ull                 // 8192*8192
#define Z_OFF    71303168ull                 // + 8192*512

// ---------------- scratch (no allocations allowed) ----------------
__device__ alignas(16) float g_XW1 [N_NODESC * NHIDC];
__device__ alignas(16) float g_HE  [N_NODESC * NHIDC];
__device__ alignas(16) float g_AGG1[N_NODESC * NHIDC];
__device__ alignas(16) float g_XW2 [N_NODESC * LATENTC];
__device__ alignas(16) float g_AGG2[N_NODESC * LATENTC];
__device__ alignas(16) float g_HD  [N_NODESC * NHIDC];

// ---------------- helpers ----------------
__device__ __forceinline__ unsigned long long pack2(float lo, float hi) {
    unsigned long long r;
    asm("mov.b64 %0, {%1, %2};" : "=l"(r) : "f"(lo), "f"(hi));
    return r;
}
__device__ __forceinline__ void ffma2(unsigned long long& d, unsigned long long a, unsigned long long b) {
    asm("fma.rn.f32x2 %0, %1, %2, %0;" : "+l"(d) : "l"(a), "l"(b));
}
__device__ __forceinline__ float2 unpack2(unsigned long long v) {
    float2 r;
    asm("mov.b64 {%0, %1}, %2;" : "=f"(r.x), "=f"(r.y) : "l"(v));
    return r;
}
__device__ __forceinline__ void red_add_v4(float* p, float4 v) {
    asm volatile("red.global.add.v4.f32 [%0], {%1, %2, %3, %4};"
                 :: "l"(p), "f"(v.x), "f"(v.y), "f"(v.z), "f"(v.w) : "memory");
}
// sigmoid via single-MUFU tanh: sig(x) = 0.5*tanh(0.5x) + 0.5
__device__ __forceinline__ float sigt(float x) {
    float t;
    asm("tanh.approx.f32 %0, %1;" : "=f"(t) : "f"(0.5f * x));
    return fmaf(0.5f, t, 0.5f);
}
__device__ __forceinline__ uint32_t smem_u32(const void* p) {
    uint32_t a;
    asm("{ .reg .u64 t; cvta.to.shared.u64 t, %1; cvt.u32.u64 %0, t; }" : "=r"(a) : "l"(p));
    return a;
}
__device__ __forceinline__ void ldsm_x4(uint32_t& r0, uint32_t& r1, uint32_t& r2, uint32_t& r3,
                                        uint32_t addr) {
    asm volatile("ldmatrix.sync.aligned.m8n8.x4.shared.b16 {%0,%1,%2,%3}, [%4];"
                 : "=r"(r0), "=r"(r1), "=r"(r2), "=r"(r3) : "r"(addr));
}
__device__ __forceinline__ void mma_16816(float* c, const uint32_t* a, const uint32_t* b) {
    asm volatile(
        "mma.sync.aligned.m16n8k16.row.col.f32.bf16.bf16.f32 "
        "{%0,%1,%2,%3}, {%4,%5,%6,%7}, {%8,%9}, {%0,%1,%2,%3};"
        : "+f"(c[0]), "+f"(c[1]), "+f"(c[2]), "+f"(c[3])
        : "r"(a[0]), "r"(a[1]), "r"(a[2]), "r"(a[3]), "r"(b[0]), "r"(b[1]));
}

// ---------------- kernels (non-adj: unchanged, proven passing) ----------------

__global__ void __launch_bounds__(256) k_transform1(
    const float* __restrict__ X, const float* __restrict__ Wg1,
    const float* __restrict__ We1, const float* __restrict__ be1)
{
    __shared__ float2 As2[32][64];
    __shared__ float  Bs [32][64];
    const int t = threadIdx.x;

    {
        const float4 z4 = make_float4(0.f, 0.f, 0.f, 0.f);
        int gi = blockIdx.x * 256 + t;
#pragma unroll
        for (int q = 0; q < 3; q++) {
            int i = gi + q * 32768;
            if (i < 65536) ((float4*)g_AGG1)[i] = z4;
            else           ((float4*)g_AGG2)[i - 65536] = z4;
        }
    }

    const int rowBase = blockIdx.x * 64;
    const int tx = t & 15, ty = t >> 4;

    unsigned long long acc[4][2];
#pragma unroll
    for (int i = 0; i < 4; i++) { acc[i][0] = 0ull; acc[i][1] = 0ull; }

    for (int k0 = 0; k0 < D_FEATC; k0 += 32) {
#pragma unroll
        for (int i = 0; i < 2; i++) {
            int idx = t + i * 256;
            int row = idx >> 3;
            int kk  = (idx & 7) * 4;
            float4 v = *(const float4*)(X + (size_t)(rowBase + row) * D_FEATC + k0 + kk);
            As2[kk + 0][row] = make_float2(v.x, v.x);
            As2[kk + 1][row] = make_float2(v.y, v.y);
            As2[kk + 2][row] = make_float2(v.z, v.z);
            As2[kk + 3][row] = make_float2(v.w, v.w);
        }
#pragma unroll
        for (int i = 0; i < 8; i++) {
            int idx = t + i * 256;
            int k = idx >> 6; int c = idx & 63;
            Bs[k][c] = (c < 32) ? Wg1[(k0 + k) * NHIDC + c]
                                : We1[(k0 + k) * NHIDC + (c - 32)];
        }
        __syncthreads();
#pragma unroll
        for (int k = 0; k < 32; k++) {
            unsigned long long a2[4];
#pragma unroll
            for (int i = 0; i < 4; i++) a2[i] = *(const unsigned long long*)&As2[k][ty * 4 + i];
            unsigned long long b2a = *(const unsigned long long*)&Bs[k][tx * 4 + 0];
            unsigned long long b2b = *(const unsigned long long*)&Bs[k][tx * 4 + 2];
#pragma unroll
            for (int i = 0; i < 4; i++) { ffma2(acc[i][0], a2[i], b2a); ffma2(acc[i][1], a2[i], b2b); }
        }
        __syncthreads();
    }

    const int c0 = tx * 4;
#pragma unroll
    for (int i = 0; i < 4; i++) {
        int row = rowBase + ty * 4 + i;
        float2 v0 = unpack2(acc[i][0]);
        float2 v1 = unpack2(acc[i][1]);
        if (c0 < 32) {
            *(float4*)&g_XW1[row * NHIDC + c0] = make_float4(v0.x, v0.y, v1.x, v1.y);
        } else {
            int cc = c0 - 32;
            float4 o;
            o.x = fmaxf(v0.x + be1[cc + 0], 0.f);
            o.y = fmaxf(v0.y + be1[cc + 1], 0.f);
            o.z = fmaxf(v1.x + be1[cc + 2], 0.f);
            o.w = fmaxf(v1.y + be1[cc + 3], 0.f);
            *(float4*)&g_HE[row * NHIDC + cc] = o;
        }
    }
}

__global__ void __launch_bounds__(256) k_agg1(
    const int* __restrict__ src, const int* __restrict__ dst, const float* __restrict__ w)
{
    int gid = blockIdx.x * 256 + threadIdx.x;
    int e = gid >> 3;
    if (e >= N_EDGESC) return;
    int c = (gid & 7) * 4;
    int s  = __ldg(&src[e]);
    int d  = __ldg(&dst[e]);
    float wt = __ldg(&w[e]);
    float4 v = *(const float4*)&g_XW1[s * NHIDC + c];
    v.x *= wt; v.y *= wt; v.z *= wt; v.w *= wt;
    red_add_v4(&g_AGG1[d * NHIDC + c], v);
}

__global__ void __launch_bounds__(256) k_layer2pre(
    const float* __restrict__ bg1, const float* __restrict__ Wg2)
{
    __shared__ float h1s[16][32];
    __shared__ float Wg2s[NHIDC * LATENTC];
    const int t = threadIdx.x;
    const int n0 = blockIdx.x * 16;
    for (int i = t; i < NHIDC * LATENTC; i += 256) Wg2s[i] = Wg2[i];
#pragma unroll
    for (int i = 0; i < 2; i++) {
        int idx = t + i * 256;
        int n = idx >> 5; int c = idx & 31;
        h1s[n][c] = fmaxf(g_AGG1[(n0 + n) * NHIDC + c] + bg1[c], 0.f);
    }
    __syncthreads();
    const int n = t >> 4, j = t & 15;
    float s = 0.f;
#pragma unroll
    for (int i = 0; i < NHIDC; i++) s += h1s[n][i] * Wg2s[i * LATENTC + j];
    g_XW2[(n0 + n) * LATENTC + j] = s;
}

__global__ void __launch_bounds__(256) k_agg2(
    const int* __restrict__ src, const int* __restrict__ dst, const float* __restrict__ w)
{
    int gid = blockIdx.x * 256 + threadIdx.x;
    int e = gid >> 2;
    if (e >= N_EDGESC) return;
    int c = (gid & 3) * 4;
    int s  = __ldg(&src[e]);
    int d  = __ldg(&dst[e]);
    float wt = __ldg(&w[e]);
    float4 v = *(const float4*)&g_XW2[s * LATENTC + c];
    v.x *= wt; v.y *= wt; v.z *= wt; v.w *= wt;
    red_add_v4(&g_AGG2[d * LATENTC + c], v);
}

__global__ void __launch_bounds__(128) k_node(
    const float* __restrict__ bg2, const float* __restrict__ We2,
    const float* __restrict__ be2, const float* __restrict__ Wd1,
    const float* __restrict__ bd1, float* __restrict__ out)
{
    __shared__ float We2s[512], Wd1s[512], be2s[16], bd1s[32], bg2s[16];
    const int t = threadIdx.x;
    for (int i = t; i < 512; i += 128) { We2s[i] = We2[i]; Wd1s[i] = Wd1[i]; }
    if (t < 16) { be2s[t] = be2[t]; bg2s[t] = bg2[t]; }
    if (t < 32) bd1s[t] = bd1[t];
    __syncthreads();

    const int n = blockIdx.x * 128 + t;
    float he[32];
#pragma unroll
    for (int i = 0; i < 8; i++) {
        float4 v = *(const float4*)&g_HE[n * NHIDC + i * 4];
        he[i * 4 + 0] = v.x; he[i * 4 + 1] = v.y; he[i * 4 + 2] = v.z; he[i * 4 + 3] = v.w;
    }
    float zx[16];
#pragma unroll
    for (int j = 0; j < 16; j++) {
        float s = be2s[j];
#pragma unroll
        for (int i = 0; i < 32; i++) s += he[i] * We2s[i * 16 + j];
        zx[j] = fmaxf(s, 0.f);
    }
    float* zo = out + Z_OFF + (size_t)n * 32;
#pragma unroll
    for (int j = 0; j < 16; j++) {
        float za = fmaxf(g_AGG2[n * LATENTC + j] + bg2s[j], 0.f);
        zo[j]      = za;
        zo[16 + j] = zx[j];
    }
#pragma unroll
    for (int i = 0; i < 32; i++) {
        float s = bd1s[i];
#pragma unroll
        for (int j = 0; j < 16; j++) s += zx[j] * Wd1s[j * 32 + i];
        g_HD[n * NHIDC + i] = fmaxf(s, 0.f);
    }
}

__global__ void __launch_bounds__(256) k_feat(
    const float* __restrict__ Wd2, const float* __restrict__ bd2, float* __restrict__ out)
{
    __shared__ float2 hds2[16][32];
    const int t = threadIdx.x;
    const int nb = blockIdx.x * 16;
#pragma unroll
    for (int i = 0; i < 2; i++) {
        int idx = t + i * 256;
        int n = idx >> 5; int c = idx & 31;
        float v = g_HD[(nb + n) * NHIDC + c];
        hds2[n][c] = make_float2(v, v);
    }
    __syncthreads();

    const int c  = t & 127;
    const int ng = (t >> 7) * 8;
    unsigned long long accA[8], accB[8];
#pragma unroll
    for (int nn = 0; nn < 8; nn++) { accA[nn] = 0ull; accB[nn] = 0ull; }

#pragma unroll
    for (int k = 0; k < 32; k++) {
        float4 wv = __ldg((const float4*)&Wd2[k * D_FEATC + c * 4]);
        unsigned long long w01 = pack2(wv.x, wv.y);
        unsigned long long w23 = pack2(wv.z, wv.w);
#pragma unroll
        for (int nn = 0; nn < 8; nn++) {
            unsigned long long h2 = *(const unsigned long long*)&hds2[ng + nn][k];
            ffma2(accA[nn], h2, w01);
            ffma2(accB[nn], h2, w23);
        }
    }
    float4 b = __ldg((const float4*)&bd2[c * 4]);
#pragma unroll
    for (int nn = 0; nn < 8; nn++) {
        float2 vA = unpack2(accA[nn]);
        float2 vB = unpack2(accB[nn]);
        float4 o;
        o.x = fmaxf(vA.x + b.x, 0.f);
        o.y = fmaxf(vA.y + b.y, 0.f);
        o.z = fmaxf(vB.x + b.z, 0.f);
        o.w = fmaxf(vB.y + b.w, 0.f);
        *(float4*)&out[FEAT_OFF + (size_t)(nb + ng + nn) * D_FEATC + c * 4] = o;
    }
}

// ---------------- warp-MMA adjacency (R6 epilogue, tanh sigmoid) ----------------
// adj = sigmoid(z z^T) via mma.sync m16n8k16 bf16, hi/lo split as K=96 GEMM:
//   A'' = [Hi | Hi | Lo], B'' = [Hi | Lo | Hi]  ->  Hi Hi^T + Hi Lo^T + Lo Hi^T
#define AW 104
#define ADJ_SMEM (2 * 128 * AW * 2)      // 53248 bytes

__global__ void __launch_bounds__(256) k_adj_wm(
    const float* __restrict__ zmat, float* __restrict__ out)
{
    extern __shared__ __nv_bfloat16 sm[];
    __nv_bfloat16* Asm = sm;                 // [128][AW]
    __nv_bfloat16* Bsm = sm + 128 * AW;      // [128][AW]

    const int t = threadIdx.x;
    const int wid = t >> 5;
    const int lane = t & 31;

    // triangular tile-pair decode
    const int T = 64;
    const int b = blockIdx.x;
    float disc = 129.0f * 129.0f - 8.0f * (float)b;
    int it = (int)((129.0f - sqrtf(disc)) * 0.5f);
    while (it > 0 && b < it * T - (it * (it - 1)) / 2) it--;
    while (b >= (it + 1) * T - ((it + 1) * it) / 2) it++;
    const int jt = it + (b - (it * T - (it * (it - 1)) / 2));

    // prologue: load z rows, bf16 hi/lo split, write padded smem (Hi duplicated)
    for (int idx = t; idx < 2048; idx += 256) {
        int half = idx >> 10;
        int rem  = idx & 1023;
        int row  = rem >> 3;
        int q    = rem & 7;
        int tl   = half ? jt : it;
        float4 v = *(const float4*)&zmat[((size_t)tl * 128 + row) * 32 + q * 4];

        __nv_bfloat16 h0 = __float2bfloat16(v.x);
        __nv_bfloat16 h1 = __float2bfloat16(v.y);
        __nv_bfloat16 h2 = __float2bfloat16(v.z);
        __nv_bfloat16 h3 = __float2bfloat16(v.w);
        __nv_bfloat16 l0 = __float2bfloat16(v.x - __bfloat162float(h0));
        __nv_bfloat16 l1 = __float2bfloat16(v.y - __bfloat162float(h1));
        __nv_bfloat16 l2 = __float2bfloat16(v.z - __bfloat162float(h2));
        __nv_bfloat16 l3 = __float2bfloat16(v.w - __bfloat162float(h3));

        __nv_bfloat162 hp0 = __nv_bfloat162(h0, h1), hp1 = __nv_bfloat162(h2, h3);
        __nv_bfloat162 lp0 = __nv_bfloat162(l0, l1), lp1 = __nv_bfloat162(l2, l3);
        uint2 hw = make_uint2(*(uint32_t*)&hp0, *(uint32_t*)&hp1);
        uint2 lw = make_uint2(*(uint32_t*)&lp0, *(uint32_t*)&lp1);

        __nv_bfloat16* base = (half ? Bsm : Asm) + row * AW + q * 4;
        if (!half) {
            *(uint2*)(base + 0)  = hw;        // Hi @ [0,32)
            *(uint2*)(base + 32) = hw;        // Hi @ [32,64)
            *(uint2*)(base + 64) = lw;        // Lo @ [64,96)
        } else {
            *(uint2*)(base + 0)  = hw;        // Hi @ [0,32)
            *(uint2*)(base + 32) = lw;        // Lo @ [32,64)
            *(uint2*)(base + 64) = hw;        // Hi @ [64,96)
        }
    }
    __syncthreads();

    const int wm = wid & 3;
    const int wn = wid >> 2;
    const int rowW = wm * 32;
    const int colW = wn * 64;

    float c[2][8][4];
#pragma unroll
    for (int mi = 0; mi < 2; mi++)
#pragma unroll
        for (int ni = 0; ni < 8; ni++)
#pragma unroll
            for (int r = 0; r < 4; r++) c[mi][ni][r] = 0.f;

    const uint32_t aBase = smem_u32(Asm);
    const uint32_t bBase = smem_u32(Bsm);
    const int la_r = lane & 15;
    const int la_c = (lane >> 4) * 8;
    const int lb_r = (lane & 7) + ((lane >> 4) * 8);
    const int lb_c = ((lane >> 3) & 1) * 8;

#pragma unroll
    for (int kc = 0; kc < 6; kc++) {
        const int k0 = kc * 16;
        uint32_t a[2][4];
#pragma unroll
        for (int mi = 0; mi < 2; mi++) {
            uint32_t addr = aBase + ((rowW + mi * 16 + la_r) * AW + k0 + la_c) * 2;
            ldsm_x4(a[mi][0], a[mi][1], a[mi][2], a[mi][3], addr);
        }
        uint32_t bfr[8][2];
#pragma unroll
        for (int nb2 = 0; nb2 < 4; nb2++) {
            uint32_t addr = bBase + ((colW + nb2 * 16 + lb_r) * AW + k0 + lb_c) * 2;
            uint32_t t0, t1, t2, t3;
            ldsm_x4(t0, t1, t2, t3, addr);
            bfr[nb2 * 2 + 0][0] = t0; bfr[nb2 * 2 + 0][1] = t1;
            bfr[nb2 * 2 + 1][0] = t2; bfr[nb2 * 2 + 1][1] = t3;
        }
#pragma unroll
        for (int mi = 0; mi < 2; mi++)
#pragma unroll
            for (int ni = 0; ni < 8; ni++)
                mma_16816(c[mi][ni], a[mi], bfr[ni]);
    }

    // epilogue (R6 direct-store form): sigmoid (tanh) + stores
    const int rThr = lane >> 2;
    const int cThr = (lane & 3) * 2;
    const size_t gi0 = (size_t)it * 128;
    const size_t gj0 = (size_t)jt * 128;

#pragma unroll
    for (int mi = 0; mi < 2; mi++) {
#pragma unroll
        for (int ni = 0; ni < 8; ni++) {
            float s0 = sigt(c[mi][ni][0]);
            float s1 = sigt(c[mi][ni][1]);
            float s2 = sigt(c[mi][ni][2]);
            float s3 = sigt(c[mi][ni][3]);
            int r0 = rowW + mi * 16 + rThr;
            int cc = colW + ni * 8 + cThr;
            *(float2*)&out[(gi0 + r0)     * (size_t)N_NODESC + gj0 + cc] = make_float2(s0, s1);
            *(float2*)&out[(gi0 + r0 + 8) * (size_t)N_NODESC + gj0 + cc] = make_float2(s2, s3);
            if (it != jt) {
                out[(gj0 + cc)     * (size_t)N_NODESC + gi0 + r0]     = s0;
                out[(gj0 + cc + 1) * (size_t)N_NODESC + gi0 + r0]     = s1;
                out[(gj0 + cc)     * (size_t)N_NODESC + gi0 + r0 + 8] = s2;
                out[(gj0 + cc + 1) * (size_t)N_NODESC + gi0 + r0 + 8] = s3;
            }
        }
    }
}

// ---------------- launch ----------------
extern "C" void kernel_launch(void* const* d_in, const int* in_sizes, int n_in,
                              void* d_out, int out_size)
{
    const float* X   = (const float*)d_in[0];
    const int*   esrc= (const int*)  d_in[1];
    const int*   edst= (const int*)  d_in[2];
    const float* ew  = (const float*)d_in[3];
    const float* Wg1 = (const float*)d_in[4];
    const float* bg1 = (const float*)d_in[5];
    const float* Wg2 = (const float*)d_in[6];
    const float* bg2 = (const float*)d_in[7];
    const float* We1 = (const float*)d_in[8];
    const float* be1 = (const float*)d_in[9];
    const float* We2 = (const float*)d_in[10];
    const float* be2 = (const float*)d_in[11];
    const float* Wd1 = (const float*)d_in[12];
    const float* bd1 = (const float*)d_in[13];
    const float* Wd2 = (const float*)d_in[14];
    const float* bd2 = (const float*)d_in[15];
    float* out = (float*)d_out;

    static int smemSet = 0;
    if (!smemSet) {
        cudaFuncSetAttribute(k_adj_wm, cudaFuncAttributeMaxDynamicSharedMemorySize, ADJ_SMEM);
        smemSet = 1;
    }

    k_transform1<<<128, 256>>>(X, Wg1, We1, be1);
    k_agg1      <<<8192, 256>>>(esrc, edst, ew);
    k_layer2pre <<<512, 256>>>(bg1, Wg2);
    k_agg2      <<<4096, 256>>>(esrc, edst, ew);
    k_node      <<<64, 128>>>(bg2, We2, be2, Wd1, bd1, out);
    k_feat      <<<512, 256>>>(Wd2, bd2, out);
    k_adj_wm    <<<2080, 256, ADJ_SMEM>>>(out + Z_OFF, out);
}

// round 10
// speedup vs baseline: 1.1503x; 1.1503x over previous
#include <cuda_runtime.h>
#include <cuda_bf16.h>
#include <cstdint>

#define N_NODESC 8192
#define N_EDGESC 262144
#define D_FEATC  512
#define NHIDC    32
#define LATENTC  16

// output layout (float elements)
#define ADJ_OFF  0ull
#define FEAT_OFF 67108864ull                 // 8192*8192
#define Z_OFF    71303168ull                 // + 8192*512

// ---------------- scratch (no allocations allowed) ----------------
__device__ alignas(16) float g_XW1 [N_NODESC * NHIDC];
__device__ alignas(16) float g_HE  [N_NODESC * NHIDC];
__device__ alignas(16) float g_AGG1[N_NODESC * NHIDC];
__device__ alignas(16) float g_XW2 [N_NODESC * LATENTC];
__device__ alignas(16) float g_AGG2[N_NODESC * LATENTC];
__device__ alignas(16) float g_HD  [N_NODESC * NHIDC];

// ---------------- helpers ----------------
__device__ __forceinline__ unsigned long long pack2(float lo, float hi) {
    unsigned long long r;
    asm("mov.b64 %0, {%1, %2};" : "=l"(r) : "f"(lo), "f"(hi));
    return r;
}
__device__ __forceinline__ void ffma2(unsigned long long& d, unsigned long long a, unsigned long long b) {
    asm("fma.rn.f32x2 %0, %1, %2, %0;" : "+l"(d) : "l"(a), "l"(b));
}
__device__ __forceinline__ float2 unpack2(unsigned long long v) {
    float2 r;
    asm("mov.b64 {%0, %1}, %2;" : "=f"(r.x), "=f"(r.y) : "l"(v));
    return r;
}
__device__ __forceinline__ void red_add_v4(float* p, float4 v) {
    asm volatile("red.global.add.v4.f32 [%0], {%1, %2, %3, %4};"
                 :: "l"(p), "f"(v.x), "f"(v.y), "f"(v.z), "f"(v.w) : "memory");
}
__device__ __forceinline__ float sigf(float x) {
    return __fdividef(1.0f, 1.0f + __expf(-x));
}
__device__ __forceinline__ uint32_t smem_u32(const void* p) {
    uint32_t a;
    asm("{ .reg .u64 t; cvta.to.shared.u64 t, %1; cvt.u32.u64 %0, t; }" : "=r"(a) : "l"(p));
    return a;
}
__device__ __forceinline__ void ldsm_x4(uint32_t& r0, uint32_t& r1, uint32_t& r2, uint32_t& r3,
                                        uint32_t addr) {
    asm volatile("ldmatrix.sync.aligned.m8n8.x4.shared.b16 {%0,%1,%2,%3}, [%4];"
                 : "=r"(r0), "=r"(r1), "=r"(r2), "=r"(r3) : "r"(addr));
}
__device__ __forceinline__ void mma_16816(float* c, const uint32_t* a, const uint32_t* b) {
    asm volatile(
        "mma.sync.aligned.m16n8k16.row.col.f32.bf16.bf16.f32 "
        "{%0,%1,%2,%3}, {%4,%5,%6,%7}, {%8,%9}, {%0,%1,%2,%3};"
        : "+f"(c[0]), "+f"(c[1]), "+f"(c[2]), "+f"(c[3])
        : "r"(a[0]), "r"(a[1]), "r"(a[2]), "r"(a[3]), "r"(b[0]), "r"(b[1]));
}

// ---------------- kernels (non-adj: unchanged, proven passing) ----------------

__global__ void __launch_bounds__(256) k_transform1(
    const float* __restrict__ X, const float* __restrict__ Wg1,
    const float* __restrict__ We1, const float* __restrict__ be1)
{
    __shared__ float2 As2[32][64];
    __shared__ float  Bs [32][64];
    const int t = threadIdx.x;

    {
        const float4 z4 = make_float4(0.f, 0.f, 0.f, 0.f);
        int gi = blockIdx.x * 256 + t;
#pragma unroll
        for (int q = 0; q < 3; q++) {
            int i = gi + q * 32768;
            if (i < 65536) ((float4*)g_AGG1)[i] = z4;
            else           ((float4*)g_AGG2)[i - 65536] = z4;
        }
    }

    const int rowBase = blockIdx.x * 64;
    const int tx = t & 15, ty = t >> 4;

    unsigned long long acc[4][2];
#pragma unroll
    for (int i = 0; i < 4; i++) { acc[i][0] = 0ull; acc[i][1] = 0ull; }

    for (int k0 = 0; k0 < D_FEATC; k0 += 32) {
#pragma unroll
        for (int i = 0; i < 2; i++) {
            int idx = t + i * 256;
            int row = idx >> 3;
            int kk  = (idx & 7) * 4;
            float4 v = *(const float4*)(X + (size_t)(rowBase + row) * D_FEATC + k0 + kk);
            As2[kk + 0][row] = make_float2(v.x, v.x);
            As2[kk + 1][row] = make_float2(v.y, v.y);
            As2[kk + 2][row] = make_float2(v.z, v.z);
            As2[kk + 3][row] = make_float2(v.w, v.w);
        }
#pragma unroll
        for (int i = 0; i < 8; i++) {
            int idx = t + i * 256;
            int k = idx >> 6; int c = idx & 63;
            Bs[k][c] = (c < 32) ? Wg1[(k0 + k) * NHIDC + c]
                                : We1[(k0 + k) * NHIDC + (c - 32)];
        }
        __syncthreads();
#pragma unroll
        for (int k = 0; k < 32; k++) {
            unsigned long long a2[4];
#pragma unroll
            for (int i = 0; i < 4; i++) a2[i] = *(const unsigned long long*)&As2[k][ty * 4 + i];
            unsigned long long b2a = *(const unsigned long long*)&Bs[k][tx * 4 + 0];
            unsigned long long b2b = *(const unsigned long long*)&Bs[k][tx * 4 + 2];
#pragma unroll
            for (int i = 0; i < 4; i++) { ffma2(acc[i][0], a2[i], b2a); ffma2(acc[i][1], a2[i], b2b); }
        }
        __syncthreads();
    }

    const int c0 = tx * 4;
#pragma unroll
    for (int i = 0; i < 4; i++) {
        int row = rowBase + ty * 4 + i;
        float2 v0 = unpack2(acc[i][0]);
        float2 v1 = unpack2(acc[i][1]);
        if (c0 < 32) {
            *(float4*)&g_XW1[row * NHIDC + c0] = make_float4(v0.x, v0.y, v1.x, v1.y);
        } else {
            int cc = c0 - 32;
            float4 o;
            o.x = fmaxf(v0.x + be1[cc + 0], 0.f);
            o.y = fmaxf(v0.y + be1[cc + 1], 0.f);
            o.z = fmaxf(v1.x + be1[cc + 2], 0.f);
            o.w = fmaxf(v1.y + be1[cc + 3], 0.f);
            *(float4*)&g_HE[row * NHIDC + cc] = o;
        }
    }
}

__global__ void __launch_bounds__(256) k_agg1(
    const int* __restrict__ src, const int* __restrict__ dst, const float* __restrict__ w)
{
    int gid = blockIdx.x * 256 + threadIdx.x;
    int e = gid >> 3;
    if (e >= N_EDGESC) return;
    int c = (gid & 7) * 4;
    int s  = __ldg(&src[e]);
    int d  = __ldg(&dst[e]);
    float wt = __ldg(&w[e]);
    float4 v = *(const float4*)&g_XW1[s * NHIDC + c];
    v.x *= wt; v.y *= wt; v.z *= wt; v.w *= wt;
    red_add_v4(&g_AGG1[d * NHIDC + c], v);
}

__global__ void __launch_bounds__(256) k_layer2pre(
    const float* __restrict__ bg1, const float* __restrict__ Wg2)
{
    __shared__ float h1s[16][32];
    __shared__ float Wg2s[NHIDC * LATENTC];
    const int t = threadIdx.x;
    const int n0 = blockIdx.x * 16;
    for (int i = t; i < NHIDC * LATENTC; i += 256) Wg2s[i] = Wg2[i];
#pragma unroll
    for (int i = 0; i < 2; i++) {
        int idx = t + i * 256;
        int n = idx >> 5; int c = idx & 31;
        h1s[n][c] = fmaxf(g_AGG1[(n0 + n) * NHIDC + c] + bg1[c], 0.f);
    }
    __syncthreads();
    const int n = t >> 4, j = t & 15;
    float s = 0.f;
#pragma unroll
    for (int i = 0; i < NHIDC; i++) s += h1s[n][i] * Wg2s[i * LATENTC + j];
    g_XW2[(n0 + n) * LATENTC + j] = s;
}

__global__ void __launch_bounds__(256) k_agg2(
    const int* __restrict__ src, const int* __restrict__ dst, const float* __restrict__ w)
{
    int gid = blockIdx.x * 256 + threadIdx.x;
    int e = gid >> 2;
    if (e >= N_EDGESC) return;
    int c = (gid & 3) * 4;
    int s  = __ldg(&src[e]);
    int d  = __ldg(&dst[e]);
    float wt = __ldg(&w[e]);
    float4 v = *(const float4*)&g_XW2[s * LATENTC + c];
    v.x *= wt; v.y *= wt; v.z *= wt; v.w *= wt;
    red_add_v4(&g_AGG2[d * LATENTC + c], v);
}

__global__ void __launch_bounds__(128) k_node(
    const float* __restrict__ bg2, const float* __restrict__ We2,
    const float* __restrict__ be2, const float* __restrict__ Wd1,
    const float* __restrict__ bd1, float* __restrict__ out)
{
    __shared__ float We2s[512], Wd1s[512], be2s[16], bd1s[32], bg2s[16];
    const int t = threadIdx.x;
    for (int i = t; i < 512; i += 128) { We2s[i] = We2[i]; Wd1s[i] = Wd1[i]; }
    if (t < 16) { be2s[t] = be2[t]; bg2s[t] = bg2[t]; }
    if (t < 32) bd1s[t] = bd1[t];
    __syncthreads();

    const int n = blockIdx.x * 128 + t;
    float he[32];
#pragma unroll
    for (int i = 0; i < 8; i++) {
        float4 v = *(const float4*)&g_HE[n * NHIDC + i * 4];
        he[i * 4 + 0] = v.x; he[i * 4 + 1] = v.y; he[i * 4 + 2] = v.z; he[i * 4 + 3] = v.w;
    }
    float zx[16];
#pragma unroll
    for (int j = 0; j < 16; j++) {
        float s = be2s[j];
#pragma unroll
        for (int i = 0; i < 32; i++) s += he[i] * We2s[i * 16 + j];
        zx[j] = fmaxf(s, 0.f);
    }
    float* zo = out + Z_OFF + (size_t)n * 32;
#pragma unroll
    for (int j = 0; j < 16; j++) {
        float za = fmaxf(g_AGG2[n * LATENTC + j] + bg2s[j], 0.f);
        zo[j]      = za;
        zo[16 + j] = zx[j];
    }
#pragma unroll
    for (int i = 0; i < 32; i++) {
        float s = bd1s[i];
#pragma unroll
        for (int j = 0; j < 16; j++) s += zx[j] * Wd1s[j * 32 + i];
        g_HD[n * NHIDC + i] = fmaxf(s, 0.f);
    }
}

__global__ void __launch_bounds__(256) k_feat(
    const float* __restrict__ Wd2, const float* __restrict__ bd2, float* __restrict__ out)
{
    __shared__ float2 hds2[16][32];
    const int t = threadIdx.x;
    const int nb = blockIdx.x * 16;
#pragma unroll
    for (int i = 0; i < 2; i++) {
        int idx = t + i * 256;
        int n = idx >> 5; int c = idx & 31;
        float v = g_HD[(nb + n) * NHIDC + c];
        hds2[n][c] = make_float2(v, v);
    }
    __syncthreads();

    const int c  = t & 127;
    const int ng = (t >> 7) * 8;
    unsigned long long accA[8], accB[8];
#pragma unroll
    for (int nn = 0; nn < 8; nn++) { accA[nn] = 0ull; accB[nn] = 0ull; }

#pragma unroll
    for (int k = 0; k < 32; k++) {
        float4 wv = __ldg((const float4*)&Wd2[k * D_FEATC + c * 4]);
        unsigned long long w01 = pack2(wv.x, wv.y);
        unsigned long long w23 = pack2(wv.z, wv.w);
#pragma unroll
        for (int nn = 0; nn < 8; nn++) {
            unsigned long long h2 = *(const unsigned long long*)&hds2[ng + nn][k];
            ffma2(accA[nn], h2, w01);
            ffma2(accB[nn], h2, w23);
        }
    }
    float4 b = __ldg((const float4*)&bd2[c * 4]);
#pragma unroll
    for (int nn = 0; nn < 8; nn++) {
        float2 vA = unpack2(accA[nn]);
        float2 vB = unpack2(accB[nn]);
        float4 o;
        o.x = fmaxf(vA.x + b.x, 0.f);
        o.y = fmaxf(vA.y + b.y, 0.f);
        o.z = fmaxf(vB.x + b.z, 0.f);
        o.w = fmaxf(vB.y + b.w, 0.f);
        *(float4*)&out[FEAT_OFF + (size_t)(nb + ng + nn) * D_FEATC + c * 4] = o;
    }
}

// ---------------- warp-MMA adjacency ----------------
// adj = sigmoid(z z^T) via mma.sync m16n8k16 bf16, hi/lo split as K=96 GEMM:
//   A'' = [Hi | Hi | Lo], B'' = [Hi | Lo | Hi]  ->  Hi Hi^T + Hi Lo^T + Lo Hi^T
// Epilogue v2: all warps sigmoid in registers (parallel), stage full 128x128 tile
// in smem [128][SW] (SW=136 -> 8B-bank row multiplier 4: STS.64 conflict-free),
// then warp-contiguous STG.128 for main rows AND transposed mirror columns.
// Store wavefronts: 1024/CTA (line-minimal) vs 4096 fragment-direct.
#define AW 104
#define SW 136
#define ADJ_SMEM (128 * SW * 4)          // 69632 bytes (A/B tiles 53248 fit inside)

__global__ void __launch_bounds__(256) k_adj_wm(
    const float* __restrict__ zmat, float* __restrict__ out)
{
    extern __shared__ __nv_bfloat16 sm[];
    __nv_bfloat16* Asm = sm;                 // [128][AW]
    __nv_bfloat16* Bsm = sm + 128 * AW;      // [128][AW]

    const int t = threadIdx.x;
    const int wid = t >> 5;
    const int lane = t & 31;

    // triangular tile-pair decode
    const int T = 64;
    const int b = blockIdx.x;
    float disc = 129.0f * 129.0f - 8.0f * (float)b;
    int it = (int)((129.0f - sqrtf(disc)) * 0.5f);
    while (it > 0 && b < it * T - (it * (it - 1)) / 2) it--;
    while (b >= (it + 1) * T - ((it + 1) * it) / 2) it++;
    const int jt = it + (b - (it * T - (it * (it - 1)) / 2));

    // prologue: load z rows, bf16 hi/lo split, write padded smem (Hi duplicated)
    for (int idx = t; idx < 2048; idx += 256) {
        int half = idx >> 10;
        int rem  = idx & 1023;
        int row  = rem >> 3;
        int q    = rem & 7;
        int tl   = half ? jt : it;
        float4 v = *(const float4*)&zmat[((size_t)tl * 128 + row) * 32 + q * 4];

        __nv_bfloat16 h0 = __float2bfloat16(v.x);
        __nv_bfloat16 h1 = __float2bfloat16(v.y);
        __nv_bfloat16 h2 = __float2bfloat16(v.z);
        __nv_bfloat16 h3 = __float2bfloat16(v.w);
        __nv_bfloat16 l0 = __float2bfloat16(v.x - __bfloat162float(h0));
        __nv_bfloat16 l1 = __float2bfloat16(v.y - __bfloat162float(h1));
        __nv_bfloat16 l2 = __float2bfloat16(v.z - __bfloat162float(h2));
        __nv_bfloat16 l3 = __float2bfloat16(v.w - __bfloat162float(h3));

        __nv_bfloat162 hp0 = __nv_bfloat162(h0, h1), hp1 = __nv_bfloat162(h2, h3);
        __nv_bfloat162 lp0 = __nv_bfloat162(l0, l1), lp1 = __nv_bfloat162(l2, l3);
        uint2 hw = make_uint2(*(uint32_t*)&hp0, *(uint32_t*)&hp1);
        uint2 lw = make_uint2(*(uint32_t*)&lp0, *(uint32_t*)&lp1);

        __nv_bfloat16* base = (half ? Bsm : Asm) + row * AW + q * 4;
        if (!half) {
            *(uint2*)(base + 0)  = hw;        // Hi @ [0,32)
            *(uint2*)(base + 32) = hw;        // Hi @ [32,64)
            *(uint2*)(base + 64) = lw;        // Lo @ [64,96)
        } else {
            *(uint2*)(base + 0)  = hw;        // Hi @ [0,32)
            *(uint2*)(base + 32) = lw;        // Lo @ [32,64)
            *(uint2*)(base + 64) = hw;        // Hi @ [64,96)
        }
    }
    __syncthreads();

    const int wm = wid & 3;
    const int wn = wid >> 2;
    const int rowW = wm * 32;
    const int colW = wn * 64;

    float c[2][8][4];
#pragma unroll
    for (int mi = 0; mi < 2; mi++)
#pragma unroll
        for (int ni = 0; ni < 8; ni++)
#pragma unroll
            for (int r = 0; r < 4; r++) c[mi][ni][r] = 0.f;

    const uint32_t aBase = smem_u32(Asm);
    const uint32_t bBase = smem_u32(Bsm);
    const int la_r = lane & 15;
    const int la_c = (lane >> 4) * 8;
    const int lb_r = (lane & 7) + ((lane >> 4) * 8);
    const int lb_c = ((lane >> 3) & 1) * 8;

#pragma unroll
    for (int kc = 0; kc < 6; kc++) {
        const int k0 = kc * 16;
        uint32_t a[2][4];
#pragma unroll
        for (int mi = 0; mi < 2; mi++) {
            uint32_t addr = aBase + ((rowW + mi * 16 + la_r) * AW + k0 + la_c) * 2;
            ldsm_x4(a[mi][0], a[mi][1], a[mi][2], a[mi][3], addr);
        }
        uint32_t bfr[8][2];
#pragma unroll
        for (int nb2 = 0; nb2 < 4; nb2++) {
            uint32_t addr = bBase + ((colW + nb2 * 16 + lb_r) * AW + k0 + lb_c) * 2;
            uint32_t t0, t1, t2, t3;
            ldsm_x4(t0, t1, t2, t3, addr);
            bfr[nb2 * 2 + 0][0] = t0; bfr[nb2 * 2 + 0][1] = t1;
            bfr[nb2 * 2 + 1][0] = t2; bfr[nb2 * 2 + 1][1] = t3;
        }
#pragma unroll
        for (int mi = 0; mi < 2; mi++)
#pragma unroll
            for (int ni = 0; ni < 8; ni++)
                mma_16816(c[mi][ni], a[mi], bfr[ni]);
    }

    // ---------------- epilogue v2 ----------------
    // 1) sigmoid in registers (all 8 warps in parallel)
#pragma unroll
    for (int mi = 0; mi < 2; mi++)
#pragma unroll
        for (int ni = 0; ni < 8; ni++)
#pragma unroll
            for (int r = 0; r < 4; r++) c[mi][ni][r] = sigf(c[mi][ni][r]);

    __syncthreads();                        // A/B tiles dead; reuse smem as stage
    float* stg = (float*)sm;                // [128][SW]
    const int rThr = lane >> 2;
    const int cThr = (lane & 3) * 2;

    // 2) stage full tile: STS.64, conflict-free (row mult 4 in 8B banks)
#pragma unroll
    for (int mi = 0; mi < 2; mi++) {
#pragma unroll
        for (int ni = 0; ni < 8; ni++) {
            int lr = rowW + mi * 16 + rThr;
            int cc = colW + ni * 8 + cThr;
            *(float2*)&stg[lr * SW + cc]       = make_float2(c[mi][ni][0], c[mi][ni][1]);
            *(float2*)&stg[(lr + 8) * SW + cc] = make_float2(c[mi][ni][2], c[mi][ni][3]);
        }
    }
    __syncthreads();

    const size_t gi0 = (size_t)it * 128;
    const size_t gj0 = (size_t)jt * 128;

    // 3) main tile: warp-contiguous rows, STG.128 (4 wf/instr)
#pragma unroll
    for (int i = 0; i < 16; i++) {
        int i2 = t + 256 * i;
        int r = i2 >> 5, g = i2 & 31;
        float4 v = *(const float4*)&stg[r * SW + g * 4];
        *(float4*)&out[(gi0 + r) * (size_t)N_NODESC + gj0 + g * 4] = v;
    }
    // 4) mirror: transposed, column LDS.32 (conflict-free), STG.128
    if (it != jt) {
#pragma unroll
        for (int i = 0; i < 16; i++) {
            int i2 = t + 256 * i;
            int cc2 = i2 & 127, q = i2 >> 7;
            float4 v = make_float4(stg[(4 * q + 0) * SW + cc2],
                                   stg[(4 * q + 1) * SW + cc2],
                                   stg[(4 * q + 2) * SW + cc2],
                                   stg[(4 * q + 3) * SW + cc2]);
            *(float4*)&out[(gj0 + cc2) * (size_t)N_NODESC + gi0 + q * 4] = v;
        }
    }
}

// ---------------- launch ----------------
extern "C" void kernel_launch(void* const* d_in, const int* in_sizes, int n_in,
                              void* d_out, int out_size)
{
    const float* X   = (const float*)d_in[0];
    const int*   esrc= (const int*)  d_in[1];
    const int*   edst= (const int*)  d_in[2];
    const float* ew  = (const float*)d_in[3];
    const float* Wg1 = (const float*)d_in[4];
    const float* bg1 = (const float*)d_in[5];
    const float* Wg2 = (const float*)d_in[6];
    const float* bg2 = (const float*)d_in[7];
    const float* We1 = (const float*)d_in[8];
    const float* be1 = (const float*)d_in[9];
    const float* We2 = (const float*)d_in[10];
    const float* be2 = (const float*)d_in[11];
    const float* Wd1 = (const float*)d_in[12];
    const float* bd1 = (const float*)d_in[13];
    const float* Wd2 = (const float*)d_in[14];
    const float* bd2 = (const float*)d_in[15];
    float* out = (float*)d_out;

    static int smemSet = 0;
    if (!smemSet) {
        cudaFuncSetAttribute(k_adj_wm, cudaFuncAttributeMaxDynamicSharedMemorySize, ADJ_SMEM);
        smemSet = 1;
    }

    k_transform1<<<128, 256>>>(X, Wg1, We1, be1);
    k_agg1      <<<8192, 256>>>(esrc, edst, ew);
    k_layer2pre <<<512, 256>>>(bg1, Wg2);
    k_agg2      <<<4096, 256>>>(esrc, edst, ew);
    k_node      <<<64, 128>>>(bg2, We2, be2, Wd1, bd1, out);
    k_feat      <<<512, 256>>>(Wd2, bd2, out);
    k_adj_wm    <<<2080, 256, ADJ_SMEM>>>(out + Z_OFF, out);
}

// round 11
// speedup vs baseline: 1.4096x; 1.2253x over previous
#include <cuda_runtime.h>
#include <cuda_bf16.h>
#include <cstdint>

#define N_NODESC 8192
#define N_EDGESC 262144
#define D_FEATC  512
#define NHIDC    32
#define LATENTC  16

// output layout (float elements)
#define ADJ_OFF  0ull
#define FEAT_OFF 67108864ull                 // 8192*8192
#define Z_OFF    71303168ull                 // + 8192*512

// ---------------- scratch (no allocations allowed) ----------------
__device__ alignas(16) float g_XW1 [N_NODESC * NHIDC];
__device__ alignas(16) float g_HE  [N_NODESC * NHIDC];
__device__ alignas(16) float g_AGG1[N_NODESC * NHIDC];
__device__ alignas(16) float g_XW2 [N_NODESC * LATENTC];
__device__ alignas(16) float g_AGG2[N_NODESC * LATENTC];
__device__ alignas(16) float g_HD  [N_NODESC * NHIDC];

// ---------------- helpers ----------------
__device__ __forceinline__ unsigned long long pack2(float lo, float hi) {
    unsigned long long r;
    asm("mov.b64 %0, {%1, %2};" : "=l"(r) : "f"(lo), "f"(hi));
    return r;
}
__device__ __forceinline__ void ffma2(unsigned long long& d, unsigned long long a, unsigned long long b) {
    asm("fma.rn.f32x2 %0, %1, %2, %0;" : "+l"(d) : "l"(a), "l"(b));
}
__device__ __forceinline__ float2 unpack2(unsigned long long v) {
    float2 r;
    asm("mov.b64 {%0, %1}, %2;" : "=f"(r.x), "=f"(r.y) : "l"(v));
    return r;
}
__device__ __forceinline__ void red_add_v4(float* p, float4 v) {
    asm volatile("red.global.add.v4.f32 [%0], {%1, %2, %3, %4};"
                 :: "l"(p), "f"(v.x), "f"(v.y), "f"(v.z), "f"(v.w) : "memory");
}
__device__ __forceinline__ float sigf(float x) {
    return __fdividef(1.0f, 1.0f + __expf(-x));
}
__device__ __forceinline__ uint32_t smem_u32(const void* p) {
    uint32_t a;
    asm("{ .reg .u64 t; cvta.to.shared.u64 t, %1; cvt.u32.u64 %0, t; }" : "=r"(a) : "l"(p));
    return a;
}
__device__ __forceinline__ void ldsm_x4(uint32_t& r0, uint32_t& r1, uint32_t& r2, uint32_t& r3,
                                        uint32_t addr) {
    asm volatile("ldmatrix.sync.aligned.m8n8.x4.shared.b16 {%0,%1,%2,%3}, [%4];"
                 : "=r"(r0), "=r"(r1), "=r"(r2), "=r"(r3) : "r"(addr));
}
__device__ __forceinline__ void mma_16816(float* c, const uint32_t* a, const uint32_t* b) {
    asm volatile(
        "mma.sync.aligned.m16n8k16.row.col.f32.bf16.bf16.f32 "
        "{%0,%1,%2,%3}, {%4,%5,%6,%7}, {%8,%9}, {%0,%1,%2,%3};"
        : "+f"(c[0]), "+f"(c[1]), "+f"(c[2]), "+f"(c[3])
        : "r"(a[0]), "r"(a[1]), "r"(a[2]), "r"(a[3]), "r"(b[0]), "r"(b[1]));
}

// ---------------- kernels (non-adj: unchanged, proven passing) ----------------

__global__ void __launch_bounds__(256) k_transform1(
    const float* __restrict__ X, const float* __restrict__ Wg1,
    const float* __restrict__ We1, const float* __restrict__ be1)
{
    __shared__ float2 As2[32][64];
    __shared__ float  Bs [32][64];
    const int t = threadIdx.x;

    {
        const float4 z4 = make_float4(0.f, 0.f, 0.f, 0.f);
        int gi = blockIdx.x * 256 + t;
#pragma unroll
        for (int q = 0; q < 3; q++) {
            int i = gi + q * 32768;
            if (i < 65536) ((float4*)g_AGG1)[i] = z4;
            else           ((float4*)g_AGG2)[i - 65536] = z4;
        }
    }

    const int rowBase = blockIdx.x * 64;
    const int tx = t & 15, ty = t >> 4;

    unsigned long long acc[4][2];
#pragma unroll
    for (int i = 0; i < 4; i++) { acc[i][0] = 0ull; acc[i][1] = 0ull; }

    for (int k0 = 0; k0 < D_FEATC; k0 += 32) {
#pragma unroll
        for (int i = 0; i < 2; i++) {
            int idx = t + i * 256;
            int row = idx >> 3;
            int kk  = (idx & 7) * 4;
            float4 v = *(const float4*)(X + (size_t)(rowBase + row) * D_FEATC + k0 + kk);
            As2[kk + 0][row] = make_float2(v.x, v.x);
            As2[kk + 1][row] = make_float2(v.y, v.y);
            As2[kk + 2][row] = make_float2(v.z, v.z);
            As2[kk + 3][row] = make_float2(v.w, v.w);
        }
#pragma unroll
        for (int i = 0; i < 8; i++) {
            int idx = t + i * 256;
            int k = idx >> 6; int c = idx & 63;
            Bs[k][c] = (c < 32) ? Wg1[(k0 + k) * NHIDC + c]
                                : We1[(k0 + k) * NHIDC + (c - 32)];
        }
        __syncthreads();
#pragma unroll
        for (int k = 0; k < 32; k++) {
            unsigned long long a2[4];
#pragma unroll
            for (int i = 0; i < 4; i++) a2[i] = *(const unsigned long long*)&As2[k][ty * 4 + i];
            unsigned long long b2a = *(const unsigned long long*)&Bs[k][tx * 4 + 0];
            unsigned long long b2b = *(const unsigned long long*)&Bs[k][tx * 4 + 2];
#pragma unroll
            for (int i = 0; i < 4; i++) { ffma2(acc[i][0], a2[i], b2a); ffma2(acc[i][1], a2[i], b2b); }
        }
        __syncthreads();
    }

    const int c0 = tx * 4;
#pragma unroll
    for (int i = 0; i < 4; i++) {
        int row = rowBase + ty * 4 + i;
        float2 v0 = unpack2(acc[i][0]);
        float2 v1 = unpack2(acc[i][1]);
        if (c0 < 32) {
            *(float4*)&g_XW1[row * NHIDC + c0] = make_float4(v0.x, v0.y, v1.x, v1.y);
        } else {
            int cc = c0 - 32;
            float4 o;
            o.x = fmaxf(v0.x + be1[cc + 0], 0.f);
            o.y = fmaxf(v0.y + be1[cc + 1], 0.f);
            o.z = fmaxf(v1.x + be1[cc + 2], 0.f);
            o.w = fmaxf(v1.y + be1[cc + 3], 0.f);
            *(float4*)&g_HE[row * NHIDC + cc] = o;
        }
    }
}

__global__ void __launch_bounds__(256) k_agg1(
    const int* __restrict__ src, const int* __restrict__ dst, const float* __restrict__ w)
{
    int gid = blockIdx.x * 256 + threadIdx.x;
    int e = gid >> 3;
    if (e >= N_EDGESC) return;
    int c = (gid & 7) * 4;
    int s  = __ldg(&src[e]);
    int d  = __ldg(&dst[e]);
    float wt = __ldg(&w[e]);
    float4 v = *(const float4*)&g_XW1[s * NHIDC + c];
    v.x *= wt; v.y *= wt; v.z *= wt; v.w *= wt;
    red_add_v4(&g_AGG1[d * NHIDC + c], v);
}

__global__ void __launch_bounds__(256) k_layer2pre(
    const float* __restrict__ bg1, const float* __restrict__ Wg2)
{
    __shared__ float h1s[16][32];
    __shared__ float Wg2s[NHIDC * LATENTC];
    const int t = threadIdx.x;
    const int n0 = blockIdx.x * 16;
    for (int i = t; i < NHIDC * LATENTC; i += 256) Wg2s[i] = Wg2[i];
#pragma unroll
    for (int i = 0; i < 2; i++) {
        int idx = t + i * 256;
        int n = idx >> 5; int c = idx & 31;
        h1s[n][c] = fmaxf(g_AGG1[(n0 + n) * NHIDC + c] + bg1[c], 0.f);
    }
    __syncthreads();
    const int n = t >> 4, j = t & 15;
    float s = 0.f;
#pragma unroll
    for (int i = 0; i < NHIDC; i++) s += h1s[n][i] * Wg2s[i * LATENTC + j];
    g_XW2[(n0 + n) * LATENTC + j] = s;
}

__global__ void __launch_bounds__(256) k_agg2(
    const int* __restrict__ src, const int* __restrict__ dst, const float* __restrict__ w)
{
    int gid = blockIdx.x * 256 + threadIdx.x;
    int e = gid >> 2;
    if (e >= N_EDGESC) return;
    int c = (gid & 3) * 4;
    int s  = __ldg(&src[e]);
    int d  = __ldg(&dst[e]);
    float wt = __ldg(&w[e]);
    float4 v = *(const float4*)&g_XW2[s * LATENTC + c];
    v.x *= wt; v.y *= wt; v.z *= wt; v.w *= wt;
    red_add_v4(&g_AGG2[d * LATENTC + c], v);
}

__global__ void __launch_bounds__(128) k_node(
    const float* __restrict__ bg2, const float* __restrict__ We2,
    const float* __restrict__ be2, const float* __restrict__ Wd1,
    const float* __restrict__ bd1, float* __restrict__ out)
{
    __shared__ float We2s[512], Wd1s[512], be2s[16], bd1s[32], bg2s[16];
    const int t = threadIdx.x;
    for (int i = t; i < 512; i += 128) { We2s[i] = We2[i]; Wd1s[i] = Wd1[i]; }
    if (t < 16) { be2s[t] = be2[t]; bg2s[t] = bg2[t]; }
    if (t < 32) bd1s[t] = bd1[t];
    __syncthreads();

    const int n = blockIdx.x * 128 + t;
    float he[32];
#pragma unroll
    for (int i = 0; i < 8; i++) {
        float4 v = *(const float4*)&g_HE[n * NHIDC + i * 4];
        he[i * 4 + 0] = v.x; he[i * 4 + 1] = v.y; he[i * 4 + 2] = v.z; he[i * 4 + 3] = v.w;
    }
    float zx[16];
#pragma unroll
    for (int j = 0; j < 16; j++) {
        float s = be2s[j];
#pragma unroll
        for (int i = 0; i < 32; i++) s += he[i] * We2s[i * 16 + j];
        zx[j] = fmaxf(s, 0.f);
    }
    float* zo = out + Z_OFF + (size_t)n * 32;
#pragma unroll
    for (int j = 0; j < 16; j++) {
        float za = fmaxf(g_AGG2[n * LATENTC + j] + bg2s[j], 0.f);
        zo[j]      = za;
        zo[16 + j] = zx[j];
    }
#pragma unroll
    for (int i = 0; i < 32; i++) {
        float s = bd1s[i];
#pragma unroll
        for (int j = 0; j < 16; j++) s += zx[j] * Wd1s[j * 32 + i];
        g_HD[n * NHIDC + i] = fmaxf(s, 0.f);
    }
}

__global__ void __launch_bounds__(256) k_feat(
    const float* __restrict__ Wd2, const float* __restrict__ bd2, float* __restrict__ out)
{
    __shared__ float2 hds2[16][32];
    const int t = threadIdx.x;
    const int nb = blockIdx.x * 16;
#pragma unroll
    for (int i = 0; i < 2; i++) {
        int idx = t + i * 256;
        int n = idx >> 5; int c = idx & 31;
        float v = g_HD[(nb + n) * NHIDC + c];
        hds2[n][c] = make_float2(v, v);
    }
    __syncthreads();

    const int c  = t & 127;
    const int ng = (t >> 7) * 8;
    unsigned long long accA[8], accB[8];
#pragma unroll
    for (int nn = 0; nn < 8; nn++) { accA[nn] = 0ull; accB[nn] = 0ull; }

#pragma unroll
    for (int k = 0; k < 32; k++) {
        float4 wv = __ldg((const float4*)&Wd2[k * D_FEATC + c * 4]);
        unsigned long long w01 = pack2(wv.x, wv.y);
        unsigned long long w23 = pack2(wv.z, wv.w);
#pragma unroll
        for (int nn = 0; nn < 8; nn++) {
            unsigned long long h2 = *(const unsigned long long*)&hds2[ng + nn][k];
            ffma2(accA[nn], h2, w01);
            ffma2(accB[nn], h2, w23);
        }
    }
    float4 b = __ldg((const float4*)&bd2[c * 4]);
#pragma unroll
    for (int nn = 0; nn < 8; nn++) {
        float2 vA = unpack2(accA[nn]);
        float2 vB = unpack2(accB[nn]);
        float4 o;
        o.x = fmaxf(vA.x + b.x, 0.f);
        o.y = fmaxf(vA.y + b.y, 0.f);
        o.z = fmaxf(vB.x + b.z, 0.f);
        o.w = fmaxf(vB.y + b.w, 0.f);
        *(float4*)&out[FEAT_OFF + (size_t)(nb + ng + nn) * D_FEATC + c * 4] = o;
    }
}

// ---------------- warp-MMA adjacency (R6 form: direct fragment stores) ----------------
// adj = sigmoid(z z^T) via mma.sync m16n8k16 bf16, hi/lo split as K=96 GEMM:
//   A'' = [Hi | Hi | Lo], B'' = [Hi | Lo | Hi]  ->  Hi Hi^T + Hi Lo^T + Lo Hi^T
#define AW 104
#define ADJ_SMEM (2 * 128 * AW * 2)      // 53248 bytes

__global__ void __launch_bounds__(256) k_adj_wm(
    const float* __restrict__ zmat, float* __restrict__ out)
{
    extern __shared__ __nv_bfloat16 sm[];
    __nv_bfloat16* Asm = sm;                 // [128][AW]
    __nv_bfloat16* Bsm = sm + 128 * AW;      // [128][AW]

    const int t = threadIdx.x;
    const int wid = t >> 5;
    const int lane = t & 31;

    // triangular tile-pair decode
    const int T = 64;
    const int b = blockIdx.x;
    float disc = 129.0f * 129.0f - 8.0f * (float)b;
    int it = (int)((129.0f - sqrtf(disc)) * 0.5f);
    while (it > 0 && b < it * T - (it * (it - 1)) / 2) it--;
    while (b >= (it + 1) * T - ((it + 1) * it) / 2) it++;
    const int jt = it + (b - (it * T - (it * (it - 1)) / 2));

    // prologue: load z rows, bf16 hi/lo split, write padded smem (Hi duplicated)
    for (int idx = t; idx < 2048; idx += 256) {
        int half = idx >> 10;
        int rem  = idx & 1023;
        int row  = rem >> 3;
        int q    = rem & 7;
        int tl   = half ? jt : it;
        float4 v = *(const float4*)&zmat[((size_t)tl * 128 + row) * 32 + q * 4];

        __nv_bfloat16 h0 = __float2bfloat16(v.x);
        __nv_bfloat16 h1 = __float2bfloat16(v.y);
        __nv_bfloat16 h2 = __float2bfloat16(v.z);
        __nv_bfloat16 h3 = __float2bfloat16(v.w);
        __nv_bfloat16 l0 = __float2bfloat16(v.x - __bfloat162float(h0));
        __nv_bfloat16 l1 = __float2bfloat16(v.y - __bfloat162float(h1));
        __nv_bfloat16 l2 = __float2bfloat16(v.z - __bfloat162float(h2));
        __nv_bfloat16 l3 = __float2bfloat16(v.w - __bfloat162float(h3));

        __nv_bfloat162 hp0 = __nv_bfloat162(h0, h1), hp1 = __nv_bfloat162(h2, h3);
        __nv_bfloat162 lp0 = __nv_bfloat162(l0, l1), lp1 = __nv_bfloat162(l2, l3);
        uint2 hw = make_uint2(*(uint32_t*)&hp0, *(uint32_t*)&hp1);
        uint2 lw = make_uint2(*(uint32_t*)&lp0, *(uint32_t*)&lp1);

        __nv_bfloat16* base = (half ? Bsm : Asm) + row * AW + q * 4;
        if (!half) {
            *(uint2*)(base + 0)  = hw;        // Hi @ [0,32)
            *(uint2*)(base + 32) = hw;        // Hi @ [32,64)
            *(uint2*)(base + 64) = lw;        // Lo @ [64,96)
        } else {
            *(uint2*)(base + 0)  = hw;        // Hi @ [0,32)
            *(uint2*)(base + 32) = lw;        // Lo @ [32,64)
            *(uint2*)(base + 64) = hw;        // Hi @ [64,96)
        }
    }
    __syncthreads();

    const int wm = wid & 3;
    const int wn = wid >> 2;
    const int rowW = wm * 32;
    const int colW = wn * 64;

    float c[2][8][4];
#pragma unroll
    for (int mi = 0; mi < 2; mi++)
#pragma unroll
        for (int ni = 0; ni < 8; ni++)
#pragma unroll
            for (int r = 0; r < 4; r++) c[mi][ni][r] = 0.f;

    const uint32_t aBase = smem_u32(Asm);
    const uint32_t bBase = smem_u32(Bsm);
    const int la_r = lane & 15;
    const int la_c = (lane >> 4) * 8;
    const int lb_r = (lane & 7) + ((lane >> 4) * 8);
    const int lb_c = ((lane >> 3) & 1) * 8;

#pragma unroll
    for (int kc = 0; kc < 6; kc++) {
        const int k0 = kc * 16;
        uint32_t a[2][4];
#pragma unroll
        for (int mi = 0; mi < 2; mi++) {
            uint32_t addr = aBase + ((rowW + mi * 16 + la_r) * AW + k0 + la_c) * 2;
            ldsm_x4(a[mi][0], a[mi][1], a[mi][2], a[mi][3], addr);
        }
        uint32_t bfr[8][2];
#pragma unroll
        for (int nb2 = 0; nb2 < 4; nb2++) {
            uint32_t addr = bBase + ((colW + nb2 * 16 + lb_r) * AW + k0 + lb_c) * 2;
            uint32_t t0, t1, t2, t3;
            ldsm_x4(t0, t1, t2, t3, addr);
            bfr[nb2 * 2 + 0][0] = t0; bfr[nb2 * 2 + 0][1] = t1;
            bfr[nb2 * 2 + 1][0] = t2; bfr[nb2 * 2 + 1][1] = t3;
        }
#pragma unroll
        for (int mi = 0; mi < 2; mi++)
#pragma unroll
            for (int ni = 0; ni < 8; ni++)
                mma_16816(c[mi][ni], a[mi], bfr[ni]);
    }

    // epilogue: sigmoid + direct fragment stores
    const int rThr = lane >> 2;
    const int cThr = (lane & 3) * 2;
    const size_t gi0 = (size_t)it * 128;
    const size_t gj0 = (size_t)jt * 128;

#pragma unroll
    for (int mi = 0; mi < 2; mi++) {
#pragma unroll
        for (int ni = 0; ni < 8; ni++) {
            float s0 = sigf(c[mi][ni][0]);
            float s1 = sigf(c[mi][ni][1]);
            float s2 = sigf(c[mi][ni][2]);
            float s3 = sigf(c[mi][ni][3]);
            int r0 = rowW + mi * 16 + rThr;
            int cc = colW + ni * 8 + cThr;
            *(float2*)&out[(gi0 + r0)     * (size_t)N_NODESC + gj0 + cc] = make_float2(s0, s1);
            *(float2*)&out[(gi0 + r0 + 8) * (size_t)N_NODESC + gj0 + cc] = make_float2(s2, s3);
            if (it != jt) {
                out[(gj0 + cc)     * (size_t)N_NODESC + gi0 + r0]     = s0;
                out[(gj0 + cc + 1) * (size_t)N_NODESC + gi0 + r0]     = s1;
                out[(gj0 + cc)     * (size_t)N_NODESC + gi0 + r0 + 8] = s2;
                out[(gj0 + cc + 1) * (size_t)N_NODESC + gi0 + r0 + 8] = s3;
            }
        }
    }
}

// ---------------- launch ----------------
extern "C" void kernel_launch(void* const* d_in, const int* in_sizes, int n_in,
                              void* d_out, int out_size)
{
    const float* X   = (const float*)d_in[0];
    const int*   esrc= (const int*)  d_in[1];
    const int*   edst= (const int*)  d_in[2];
    const float* ew  = (const float*)d_in[3];
    const float* Wg1 = (const float*)d_in[4];
    const float* bg1 = (const float*)d_in[5];
    const float* Wg2 = (const float*)d_in[6];
    const float* bg2 = (const float*)d_in[7];
    const float* We1 = (const float*)d_in[8];
    const float* be1 = (const float*)d_in[9];
    const float* We2 = (const float*)d_in[10];
    const float* be2 = (const float*)d_in[11];
    const float* Wd1 = (const float*)d_in[12];
    const float* bd1 = (const float*)d_in[13];
    const float* Wd2 = (const float*)d_in[14];
    const float* bd2 = (const float*)d_in[15];
    float* out = (float*)d_out;

    static int smemSet = 0;
    if (!smemSet) {
        cudaFuncSetAttribute(k_adj_wm, cudaFuncAttributeMaxDynamicSharedMemorySize, ADJ_SMEM);
        smemSet = 1;
    }

    k_transform1<<<128, 256>>>(X, Wg1, We1, be1);
    k_agg1      <<<8192, 256>>>(esrc, edst, ew);
    k_layer2pre <<<512, 256>>>(bg1, Wg2);
    k_agg2      <<<4096, 256>>>(esrc, edst, ew);
    k_node      <<<64, 128>>>(bg2, We2, be2, Wd1, bd1, out);
    k_feat      <<<512, 256>>>(Wd2, bd2, out);
    k_adj_wm    <<<2080, 256, ADJ_SMEM>>>(out + Z_OFF, out);
}

// round 13
// speedup vs baseline: 1.4352x; 1.0182x over previous
#include <cuda_runtime.h>
#include <cuda_bf16.h>
#include <cstdint>

#define N_NODESC 8192
#define N_EDGESC 262144
#define D_FEATC  512
#define NHIDC    32
#define LATENTC  16

// output layout (float elements)
#define ADJ_OFF  0ull
#define FEAT_OFF 67108864ull                 // 8192*8192
#define Z_OFF    71303168ull                 // + 8192*512

// ---------------- scratch (no allocations allowed) ----------------
__device__ alignas(16) float g_XW1 [N_NODESC * NHIDC];
__device__ alignas(16) float g_HE  [N_NODESC * NHIDC];
__device__ alignas(16) float g_AGG1[N_NODESC * NHIDC];
__device__ alignas(16) float g_XW2 [N_NODESC * LATENTC];
__device__ alignas(16) float g_AGG2[N_NODESC * LATENTC];
__device__ alignas(16) float g_HD  [N_NODESC * NHIDC];

// ---------------- helpers ----------------
__device__ __forceinline__ unsigned long long pack2(float lo, float hi) {
    unsigned long long r;
    asm("mov.b64 %0, {%1, %2};" : "=l"(r) : "f"(lo), "f"(hi));
    return r;
}
__device__ __forceinline__ void ffma2(unsigned long long& d, unsigned long long a, unsigned long long b) {
    asm("fma.rn.f32x2 %0, %1, %2, %0;" : "+l"(d) : "l"(a), "l"(b));
}
__device__ __forceinline__ float2 unpack2(unsigned long long v) {
    float2 r;
    asm("mov.b64 {%0, %1}, %2;" : "=f"(r.x), "=f"(r.y) : "l"(v));
    return r;
}
__device__ __forceinline__ void red_add_v4(float* p, float4 v) {
    asm volatile("red.global.add.v4.f32 [%0], {%1, %2, %3, %4};"
                 :: "l"(p), "f"(v.x), "f"(v.y), "f"(v.z), "f"(v.w) : "memory");
}
__device__ __forceinline__ float sigf(float x) {
    return __fdividef(1.0f, 1.0f + __expf(-x));
}
__device__ __forceinline__ uint32_t smem_u32(const void* p) {
    uint32_t a;
    asm("{ .reg .u64 t; cvta.to.shared.u64 t, %1; cvt.u32.u64 %0, t; }" : "=r"(a) : "l"(p));
    return a;
}
__device__ __forceinline__ void ldsm_x4(uint32_t& r0, uint32_t& r1, uint32_t& r2, uint32_t& r3,
                                        uint32_t addr) {
    asm volatile("ldmatrix.sync.aligned.m8n8.x4.shared.b16 {%0,%1,%2,%3}, [%4];"
                 : "=r"(r0), "=r"(r1), "=r"(r2), "=r"(r3) : "r"(addr));
}
__device__ __forceinline__ void mma_16816(float* c, const uint32_t* a, const uint32_t* b) {
    asm volatile(
        "mma.sync.aligned.m16n8k16.row.col.f32.bf16.bf16.f32 "
        "{%0,%1,%2,%3}, {%4,%5,%6,%7}, {%8,%9}, {%0,%1,%2,%3};"
        : "+f"(c[0]), "+f"(c[1]), "+f"(c[2]), "+f"(c[3])
        : "r"(a[0]), "r"(a[1]), "r"(a[2]), "r"(a[3]), "r"(b[0]), "r"(b[1]));
}

// ---------------- kernels (non-adj: unchanged, proven passing) ----------------

__global__ void __launch_bounds__(256) k_transform1(
    const float* __restrict__ X, const float* __restrict__ Wg1,
    const float* __restrict__ We1, const float* __restrict__ be1)
{
    __shared__ float2 As2[32][64];
    __shared__ float  Bs [32][64];
    const int t = threadIdx.x;

    {
        const float4 z4 = make_float4(0.f, 0.f, 0.f, 0.f);
        int gi = blockIdx.x * 256 + t;
#pragma unroll
        for (int q = 0; q < 3; q++) {
            int i = gi + q * 32768;
            if (i < 65536) ((float4*)g_AGG1)[i] = z4;
            else           ((float4*)g_AGG2)[i - 65536] = z4;
        }
    }

    const int rowBase = blockIdx.x * 64;
    const int tx = t & 15, ty = t >> 4;

    unsigned long long acc[4][2];
#pragma unroll
    for (int i = 0; i < 4; i++) { acc[i][0] = 0ull; acc[i][1] = 0ull; }

    for (int k0 = 0; k0 < D_FEATC; k0 += 32) {
#pragma unroll
        for (int i = 0; i < 2; i++) {
            int idx = t + i * 256;
            int row = idx >> 3;
            int kk  = (idx & 7) * 4;
            float4 v = *(const float4*)(X + (size_t)(rowBase + row) * D_FEATC + k0 + kk);
            As2[kk + 0][row] = make_float2(v.x, v.x);
            As2[kk + 1][row] = make_float2(v.y, v.y);
            As2[kk + 2][row] = make_float2(v.z, v.z);
            As2[kk + 3][row] = make_float2(v.w, v.w);
        }
#pragma unroll
        for (int i = 0; i < 8; i++) {
            int idx = t + i * 256;
            int k = idx >> 6; int c = idx & 63;
            Bs[k][c] = (c < 32) ? Wg1[(k0 + k) * NHIDC + c]
                                : We1[(k0 + k) * NHIDC + (c - 32)];
        }
        __syncthreads();
#pragma unroll
        for (int k = 0; k < 32; k++) {
            unsigned long long a2[4];
#pragma unroll
            for (int i = 0; i < 4; i++) a2[i] = *(const unsigned long long*)&As2[k][ty * 4 + i];
            unsigned long long b2a = *(const unsigned long long*)&Bs[k][tx * 4 + 0];
            unsigned long long b2b = *(const unsigned long long*)&Bs[k][tx * 4 + 2];
#pragma unroll
            for (int i = 0; i < 4; i++) { ffma2(acc[i][0], a2[i], b2a); ffma2(acc[i][1], a2[i], b2b); }
        }
        __syncthreads();
    }

    const int c0 = tx * 4;
#pragma unroll
    for (int i = 0; i < 4; i++) {
        int row = rowBase + ty * 4 + i;
        float2 v0 = unpack2(acc[i][0]);
        float2 v1 = unpack2(acc[i][1]);
        if (c0 < 32) {
            *(float4*)&g_XW1[row * NHIDC + c0] = make_float4(v0.x, v0.y, v1.x, v1.y);
        } else {
            int cc = c0 - 32;
            float4 o;
            o.x = fmaxf(v0.x + be1[cc + 0], 0.f);
            o.y = fmaxf(v0.y + be1[cc + 1], 0.f);
            o.z = fmaxf(v1.x + be1[cc + 2], 0.f);
            o.w = fmaxf(v1.y + be1[cc + 3], 0.f);
            *(float4*)&g_HE[row * NHIDC + cc] = o;
        }
    }
}

__global__ void __launch_bounds__(256) k_agg1(
    const int* __restrict__ src, const int* __restrict__ dst, const float* __restrict__ w)
{
    int gid = blockIdx.x * 256 + threadIdx.x;
    int e = gid >> 3;
    if (e >= N_EDGESC) return;
    int c = (gid & 7) * 4;
    int s  = __ldg(&src[e]);
    int d  = __ldg(&dst[e]);
    float wt = __ldg(&w[e]);
    float4 v = *(const float4*)&g_XW1[s * NHIDC + c];
    v.x *= wt; v.y *= wt; v.z *= wt; v.w *= wt;
    red_add_v4(&g_AGG1[d * NHIDC + c], v);
}

__global__ void __launch_bounds__(256) k_layer2pre(
    const float* __restrict__ bg1, const float* __restrict__ Wg2)
{
    __shared__ float h1s[16][32];
    __shared__ float Wg2s[NHIDC * LATENTC];
    const int t = threadIdx.x;
    const int n0 = blockIdx.x * 16;
    for (int i = t; i < NHIDC * LATENTC; i += 256) Wg2s[i] = Wg2[i];
#pragma unroll
    for (int i = 0; i < 2; i++) {
        int idx = t + i * 256;
        int n = idx >> 5; int c = idx & 31;
        h1s[n][c] = fmaxf(g_AGG1[(n0 + n) * NHIDC + c] + bg1[c], 0.f);
    }
    __syncthreads();
    const int n = t >> 4, j = t & 15;
    float s = 0.f;
#pragma unroll
    for (int i = 0; i < NHIDC; i++) s += h1s[n][i] * Wg2s[i * LATENTC + j];
    g_XW2[(n0 + n) * LATENTC + j] = s;
}

__global__ void __launch_bounds__(256) k_agg2(
    const int* __restrict__ src, const int* __restrict__ dst, const float* __restrict__ w)
{
    int gid = blockIdx.x * 256 + threadIdx.x;
    int e = gid >> 2;
    if (e >= N_EDGESC) return;
    int c = (gid & 3) * 4;
    int s  = __ldg(&src[e]);
    int d  = __ldg(&dst[e]);
    float wt = __ldg(&w[e]);
    float4 v = *(const float4*)&g_XW2[s * LATENTC + c];
    v.x *= wt; v.y *= wt; v.z *= wt; v.w *= wt;
    red_add_v4(&g_AGG2[d * LATENTC + c], v);
}

__global__ void __launch_bounds__(128) k_node(
    const float* __restrict__ bg2, const float* __restrict__ We2,
    const float* __restrict__ be2, const float* __restrict__ Wd1,
    const float* __restrict__ bd1, float* __restrict__ out)
{
    __shared__ float We2s[512], Wd1s[512], be2s[16], bd1s[32], bg2s[16];
    const int t = threadIdx.x;
    for (int i = t; i < 512; i += 128) { We2s[i] = We2[i]; Wd1s[i] = Wd1[i]; }
    if (t < 16) { be2s[t] = be2[t]; bg2s[t] = bg2[t]; }
    if (t < 32) bd1s[t] = bd1[t];
    __syncthreads();

    const int n = blockIdx.x * 128 + t;
    float he[32];
#pragma unroll
    for (int i = 0; i < 8; i++) {
        float4 v = *(const float4*)&g_HE[n * NHIDC + i * 4];
        he[i * 4 + 0] = v.x; he[i * 4 + 1] = v.y; he[i * 4 + 2] = v.z; he[i * 4 + 3] = v.w;
    }
    float zx[16];
#pragma unroll
    for (int j = 0; j < 16; j++) {
        float s = be2s[j];
#pragma unroll
        for (int i = 0; i < 32; i++) s += he[i] * We2s[i * 16 + j];
        zx[j] = fmaxf(s, 0.f);
    }
    float* zo = out + Z_OFF + (size_t)n * 32;
#pragma unroll
    for (int j = 0; j < 16; j++) {
        float za = fmaxf(g_AGG2[n * LATENTC + j] + bg2s[j], 0.f);
        zo[j]      = za;
        zo[16 + j] = zx[j];
    }
#pragma unroll
    for (int i = 0; i < 32; i++) {
        float s = bd1s[i];
#pragma unroll
        for (int j = 0; j < 16; j++) s += zx[j] * Wd1s[j * 32 + i];
        g_HD[n * NHIDC + i] = fmaxf(s, 0.f);
    }
}

__global__ void __launch_bounds__(256) k_feat(
    const float* __restrict__ Wd2, const float* __restrict__ bd2, float* __restrict__ out)
{
    __shared__ float2 hds2[16][32];
    const int t = threadIdx.x;
    const int nb = blockIdx.x * 16;
#pragma unroll
    for (int i = 0; i < 2; i++) {
        int idx = t + i * 256;
        int n = idx >> 5; int c = idx & 31;
        float v = g_HD[(nb + n) * NHIDC + c];
        hds2[n][c] = make_float2(v, v);
    }
    __syncthreads();

    const int c  = t & 127;
    const int ng = (t >> 7) * 8;
    unsigned long long accA[8], accB[8];
#pragma unroll
    for (int nn = 0; nn < 8; nn++) { accA[nn] = 0ull; accB[nn] = 0ull; }

#pragma unroll
    for (int k = 0; k < 32; k++) {
        float4 wv = __ldg((const float4*)&Wd2[k * D_FEATC + c * 4]);
        unsigned long long w01 = pack2(wv.x, wv.y);
        unsigned long long w23 = pack2(wv.z, wv.w);
#pragma unroll
        for (int nn = 0; nn < 8; nn++) {
            unsigned long long h2 = *(const unsigned long long*)&hds2[ng + nn][k];
            ffma2(accA[nn], h2, w01);
            ffma2(accB[nn], h2, w23);
        }
    }
    float4 b = __ldg((const float4*)&bd2[c * 4]);
#pragma unroll
    for (int nn = 0; nn < 8; nn++) {
        float2 vA = unpack2(accA[nn]);
        float2 vB = unpack2(accB[nn]);
        float4 o;
        o.x = fmaxf(vA.x + b.x, 0.f);
        o.y = fmaxf(vA.y + b.y, 0.f);
        o.z = fmaxf(vB.x + b.z, 0.f);
        o.w = fmaxf(vB.y + b.w, 0.f);
        *(float4*)&out[FEAT_OFF + (size_t)(nb + ng + nn) * D_FEATC + c * 4] = o;
    }
}

// ---------------- warp-MMA adjacency (compact [Hi|Lo] smem, 6 CTAs/SM) ----------------
// adj = sigmoid(z z^T) via mma.sync m16n8k16 bf16, hi/lo split.
// Compact layout: A = B = [Hi(cols 0..31) | Lo(cols 32..63)], AW=72 (144B stride:
// 8 ldmatrix rows walk all eight 16B segments of a 128B line -> conflict-free).
// K-chunk pairs (same products, same order as the duplicated layout):
//   (aOff,bOff) = (0,0),(16,16),(0,32),(16,48),(32,0),(48,16)
//   = HiHi(k0-15), HiHi(k16-31), HiLo(k0-15), HiLo(k16-31), LoHi(k0-15), LoHi(k16-31)
// Smem 36864B -> 6 CTAs/SM (was 53248B -> 4). Epilogue identical to R6.
#define AW 72
#define ADJ_SMEM (2 * 128 * AW * 2)      // 36864 bytes

__global__ void __launch_bounds__(256) k_adj_wm(
    const float* __restrict__ zmat, float* __restrict__ out)
{
    extern __shared__ __nv_bfloat16 sm[];
    __nv_bfloat16* Asm = sm;                 // [128][AW]
    __nv_bfloat16* Bsm = sm + 128 * AW;      // [128][AW]

    const int t = threadIdx.x;
    const int wid = t >> 5;
    const int lane = t & 31;

    // triangular tile-pair decode
    const int T = 64;
    const int b = blockIdx.x;
    float disc = 129.0f * 129.0f - 8.0f * (float)b;
    int it = (int)((129.0f - sqrtf(disc)) * 0.5f);
    while (it > 0 && b < it * T - (it * (it - 1)) / 2) it--;
    while (b >= (it + 1) * T - ((it + 1) * it) / 2) it++;
    const int jt = it + (b - (it * T - (it * (it - 1)) / 2));

    // prologue: load z rows, bf16 hi/lo split, compact [Hi|Lo] layout (both tiles)
    for (int idx = t; idx < 2048; idx += 256) {
        int half = idx >> 10;
        int rem  = idx & 1023;
        int row  = rem >> 3;
        int q    = rem & 7;
        int tl   = half ? jt : it;
        float4 v = *(const float4*)&zmat[((size_t)tl * 128 + row) * 32 + q * 4];

        __nv_bfloat16 h0 = __float2bfloat16(v.x);
        __nv_bfloat16 h1 = __float2bfloat16(v.y);
        __nv_bfloat16 h2 = __float2bfloat16(v.z);
        __nv_bfloat16 h3 = __float2bfloat16(v.w);
        __nv_bfloat16 l0 = __float2bfloat16(v.x - __bfloat162float(h0));
        __nv_bfloat16 l1 = __float2bfloat16(v.y - __bfloat162float(h1));
        __nv_bfloat16 l2 = __float2bfloat16(v.z - __bfloat162float(h2));
        __nv_bfloat16 l3 = __float2bfloat16(v.w - __bfloat162float(h3));

        __nv_bfloat162 hp0 = __nv_bfloat162(h0, h1), hp1 = __nv_bfloat162(h2, h3);
        __nv_bfloat162 lp0 = __nv_bfloat162(l0, l1), lp1 = __nv_bfloat162(l2, l3);
        uint2 hw = make_uint2(*(uint32_t*)&hp0, *(uint32_t*)&hp1);
        uint2 lw = make_uint2(*(uint32_t*)&lp0, *(uint32_t*)&lp1);

        __nv_bfloat16* base = (half ? Bsm : Asm) + row * AW + q * 4;
        *(uint2*)(base + 0)  = hw;            // Hi @ [0,32)
        *(uint2*)(base + 32) = lw;            // Lo @ [32,64)
    }
    __syncthreads();

    const int wm = wid & 3;
    const int wn = wid >> 2;
    const int rowW = wm * 32;
    const int colW = wn * 64;

    float c[2][8][4];
#pragma unroll
    for (int mi = 0; mi < 2; mi++)
#pragma unroll
        for (int ni = 0; ni < 8; ni++)
#pragma unroll
            for (int r = 0; r < 4; r++) c[mi][ni][r] = 0.f;

    const uint32_t aBase = smem_u32(Asm);
    const uint32_t bBase = smem_u32(Bsm);
    const int la_r = lane & 15;
    const int la_c = (lane >> 4) * 8;
    const int lb_r = (lane & 7) + ((lane >> 4) * 8);
    const int lb_c = ((lane >> 3) & 1) * 8;

    const int aOffs[6] = {0, 16, 0, 16, 32, 48};
    const int bOffs[6] = {0, 16, 32, 48, 0, 16};

#pragma unroll
    for (int kc = 0; kc < 6; kc++) {
        const int ka = aOffs[kc];
        const int kb = bOffs[kc];
        uint32_t a[2][4];
#pragma unroll
        for (int mi = 0; mi < 2; mi++) {
            uint32_t addr = aBase + ((rowW + mi * 16 + la_r) * AW + ka + la_c) * 2;
            ldsm_x4(a[mi][0], a[mi][1], a[mi][2], a[mi][3], addr);
        }
        uint32_t bfr[8][2];
#pragma unroll
        for (int nb2 = 0; nb2 < 4; nb2++) {
            uint32_t addr = bBase + ((colW + nb2 * 16 + lb_r) * AW + kb + lb_c) * 2;
            uint32_t t0, t1, t2, t3;
            ldsm_x4(t0, t1, t2, t3, addr);
            bfr[nb2 * 2 + 0][0] = t0; bfr[nb2 * 2 + 0][1] = t1;
            bfr[nb2 * 2 + 1][0] = t2; bfr[nb2 * 2 + 1][1] = t3;
        }
#pragma unroll
        for (int mi = 0; mi < 2; mi++)
#pragma unroll
            for (int ni = 0; ni < 8; ni++)
                mma_16816(c[mi][ni], a[mi], bfr[ni]);
    }

    // epilogue: sigmoid + direct fragment stores (R6 form)
    const int rThr = lane >> 2;
    const int cThr = (lane & 3) * 2;
    const size_t gi0 = (size_t)it * 128;
    const size_t gj0 = (size_t)jt * 128;

#pragma unroll
    for (int mi = 0; mi < 2; mi++) {
#pragma unroll
        for (int ni = 0; ni < 8; ni++) {
            float s0 = sigf(c[mi][ni][0]);
            float s1 = sigf(c[mi][ni][1]);
            float s2 = sigf(c[mi][ni][2]);
            float s3 = sigf(c[mi][ni][3]);
            int r0 = rowW + mi * 16 + rThr;
            int cc = colW + ni * 8 + cThr;
            *(float2*)&out[(gi0 + r0)     * (size_t)N_NODESC + gj0 + cc] = make_float2(s0, s1);
            *(float2*)&out[(gi0 + r0 + 8) * (size_t)N_NODESC + gj0 + cc] = make_float2(s2, s3);
            if (it != jt) {
                out[(gj0 + cc)     * (size_t)N_NODESC + gi0 + r0]     = s0;
                out[(gj0 + cc + 1) * (size_t)N_NODESC + gi0 + r0]     = s1;
                out[(gj0 + cc)     * (size_t)N_NODESC + gi0 + r0 + 8] = s2;
                out[(gj0 + cc + 1) * (size_t)N_NODESC + gi0 + r0 + 8] = s3;
            }
        }
    }
}

// ---------------- launch ----------------
extern "C" void kernel_launch(void* const* d_in, const int* in_sizes, int n_in,
                              void* d_out, int out_size)
{
    const float* X   = (const float*)d_in[0];
    const int*   esrc= (const int*)  d_in[1];
    const int*   edst= (const int*)  d_in[2];
    const float* ew  = (const float*)d_in[3];
    const float* Wg1 = (const float*)d_in[4];
    const float* bg1 = (const float*)d_in[5];
    const float* Wg2 = (const float*)d_in[6];
    const float* bg2 = (const float*)d_in[7];
    const float* We1 = (const float*)d_in[8];
    const float* be1 = (const float*)d_in[9];
    const float* We2 = (const float*)d_in[10];
    const float* be2 = (const float*)d_in[11];
    const float* Wd1 = (const float*)d_in[12];
    const float* bd1 = (const float*)d_in[13];
    const float* Wd2 = (const float*)d_in[14];
    const float* bd2 = (const float*)d_in[15];
    float* out = (float*)d_out;

    static int smemSet = 0;
    if (!smemSet) {
        cudaFuncSetAttribute(k_adj_wm, cudaFuncAttributeMaxDynamicSharedMemorySize, ADJ_SMEM);
        smemSet = 1;
    }

    k_transform1<<<128, 256>>>(X, Wg1, We1, be1);
    k_agg1      <<<8192, 256>>>(esrc, edst, ew);
    k_layer2pre <<<512, 256>>>(bg1, Wg2);
    k_agg2      <<<4096, 256>>>(esrc, edst, ew);
    k_node      <<<64, 128>>>(bg2, We2, be2, Wd1, bd1, out);
    k_feat      <<<512, 256>>>(Wd2, bd2, out);
    k_adj_wm    <<<2080, 256, ADJ_SMEM>>>(out + Z_OFF, out);
}

// round 14
// speedup vs baseline: 1.4887x; 1.0373x over previous
#include <cuda_runtime.h>
#include <cuda_bf16.h>
#include <cstdint>

#define N_NODESC 8192
#define N_EDGESC 262144
#define D_FEATC  512
#define NHIDC    32
#define LATENTC  16

// output layout (float elements)
#define ADJ_OFF  0ull
#define FEAT_OFF 67108864ull                 // 8192*8192
#define Z_OFF    71303168ull                 // + 8192*512

// ---------------- scratch (no allocations allowed) ----------------
__device__ alignas(16) float g_XW1 [N_NODESC * NHIDC];
__device__ alignas(16) float g_HE  [N_NODESC * NHIDC];
__device__ alignas(16) float g_AGG1[N_NODESC * NHIDC];
__device__ alignas(16) float g_XW2 [N_NODESC * LATENTC];
__device__ alignas(16) float g_AGG2[N_NODESC * LATENTC];
__device__ alignas(16) float g_HD  [N_NODESC * NHIDC];

// ---------------- helpers ----------------
__device__ __forceinline__ unsigned long long pack2(float lo, float hi) {
    unsigned long long r;
    asm("mov.b64 %0, {%1, %2};" : "=l"(r) : "f"(lo), "f"(hi));
    return r;
}
__device__ __forceinline__ void ffma2(unsigned long long& d, unsigned long long a, unsigned long long b) {
    asm("fma.rn.f32x2 %0, %1, %2, %0;" : "+l"(d) : "l"(a), "l"(b));
}
__device__ __forceinline__ float2 unpack2(unsigned long long v) {
    float2 r;
    asm("mov.b64 {%0, %1}, %2;" : "=f"(r.x), "=f"(r.y) : "l"(v));
    return r;
}
__device__ __forceinline__ void red_add_v4(float* p, float4 v) {
    asm volatile("red.global.add.v4.f32 [%0], {%1, %2, %3, %4};"
                 :: "l"(p), "f"(v.x), "f"(v.y), "f"(v.z), "f"(v.w) : "memory");
}
__device__ __forceinline__ float sigf(float x) {
    return __fdividef(1.0f, 1.0f + __expf(-x));
}
__device__ __forceinline__ uint32_t smem_u32(const void* p) {
    uint32_t a;
    asm("{ .reg .u64 t; cvta.to.shared.u64 t, %1; cvt.u32.u64 %0, t; }" : "=r"(a) : "l"(p));
    return a;
}
__device__ __forceinline__ void ldsm_x4(uint32_t& r0, uint32_t& r1, uint32_t& r2, uint32_t& r3,
                                        uint32_t addr) {
    asm volatile("ldmatrix.sync.aligned.m8n8.x4.shared.b16 {%0,%1,%2,%3}, [%4];"
                 : "=r"(r0), "=r"(r1), "=r"(r2), "=r"(r3) : "r"(addr));
}
__device__ __forceinline__ void mma_16816(float* c, const uint32_t* a, const uint32_t* b) {
    asm volatile(
        "mma.sync.aligned.m16n8k16.row.col.f32.bf16.bf16.f32 "
        "{%0,%1,%2,%3}, {%4,%5,%6,%7}, {%8,%9}, {%0,%1,%2,%3};"
        : "+f"(c[0]), "+f"(c[1]), "+f"(c[2]), "+f"(c[3])
        : "r"(a[0]), "r"(a[1]), "r"(a[2]), "r"(a[3]), "r"(b[0]), "r"(b[1]));
}

// ---------------- kernels (non-adj: unchanged, proven passing) ----------------

__global__ void __launch_bounds__(256) k_transform1(
    const float* __restrict__ X, const float* __restrict__ Wg1,
    const float* __restrict__ We1, const float* __restrict__ be1)
{
    __shared__ float2 As2[32][64];
    __shared__ float  Bs [32][64];
    const int t = threadIdx.x;

    {
        const float4 z4 = make_float4(0.f, 0.f, 0.f, 0.f);
        int gi = blockIdx.x * 256 + t;
#pragma unroll
        for (int q = 0; q < 3; q++) {
            int i = gi + q * 32768;
            if (i < 65536) ((float4*)g_AGG1)[i] = z4;
            else           ((float4*)g_AGG2)[i - 65536] = z4;
        }
    }

    const int rowBase = blockIdx.x * 64;
    const int tx = t & 15, ty = t >> 4;

    unsigned long long acc[4][2];
#pragma unroll
    for (int i = 0; i < 4; i++) { acc[i][0] = 0ull; acc[i][1] = 0ull; }

    for (int k0 = 0; k0 < D_FEATC; k0 += 32) {
#pragma unroll
        for (int i = 0; i < 2; i++) {
            int idx = t + i * 256;
            int row = idx >> 3;
            int kk  = (idx & 7) * 4;
            float4 v = *(const float4*)(X + (size_t)(rowBase + row) * D_FEATC + k0 + kk);
            As2[kk + 0][row] = make_float2(v.x, v.x);
            As2[kk + 1][row] = make_float2(v.y, v.y);
            As2[kk + 2][row] = make_float2(v.z, v.z);
            As2[kk + 3][row] = make_float2(v.w, v.w);
        }
#pragma unroll
        for (int i = 0; i < 8; i++) {
            int idx = t + i * 256;
            int k = idx >> 6; int c = idx & 63;
            Bs[k][c] = (c < 32) ? Wg1[(k0 + k) * NHIDC + c]
                                : We1[(k0 + k) * NHIDC + (c - 32)];
        }
        __syncthreads();
#pragma unroll
        for (int k = 0; k < 32; k++) {
            unsigned long long a2[4];
#pragma unroll
            for (int i = 0; i < 4; i++) a2[i] = *(const unsigned long long*)&As2[k][ty * 4 + i];
            unsigned long long b2a = *(const unsigned long long*)&Bs[k][tx * 4 + 0];
            unsigned long long b2b = *(const unsigned long long*)&Bs[k][tx * 4 + 2];
#pragma unroll
            for (int i = 0; i < 4; i++) { ffma2(acc[i][0], a2[i], b2a); ffma2(acc[i][1], a2[i], b2b); }
        }
        __syncthreads();
    }

    const int c0 = tx * 4;
#pragma unroll
    for (int i = 0; i < 4; i++) {
        int row = rowBase + ty * 4 + i;
        float2 v0 = unpack2(acc[i][0]);
        float2 v1 = unpack2(acc[i][1]);
        if (c0 < 32) {
            *(float4*)&g_XW1[row * NHIDC + c0] = make_float4(v0.x, v0.y, v1.x, v1.y);
        } else {
            int cc = c0 - 32;
            float4 o;
            o.x = fmaxf(v0.x + be1[cc + 0], 0.f);
            o.y = fmaxf(v0.y + be1[cc + 1], 0.f);
            o.z = fmaxf(v1.x + be1[cc + 2], 0.f);
            o.w = fmaxf(v1.y + be1[cc + 3], 0.f);
            *(float4*)&g_HE[row * NHIDC + cc] = o;
        }
    }
}

__global__ void __launch_bounds__(256) k_agg1(
    const int* __restrict__ src, const int* __restrict__ dst, const float* __restrict__ w)
{
    int gid = blockIdx.x * 256 + threadIdx.x;
    int e = gid >> 3;
    if (e >= N_EDGESC) return;
    int c = (gid & 7) * 4;
    int s  = __ldg(&src[e]);
    int d  = __ldg(&dst[e]);
    float wt = __ldg(&w[e]);
    float4 v = *(const float4*)&g_XW1[s * NHIDC + c];
    v.x *= wt; v.y *= wt; v.z *= wt; v.w *= wt;
    red_add_v4(&g_AGG1[d * NHIDC + c], v);
}

__global__ void __launch_bounds__(256) k_layer2pre(
    const float* __restrict__ bg1, const float* __restrict__ Wg2)
{
    __shared__ float h1s[16][32];
    __shared__ float Wg2s[NHIDC * LATENTC];
    const int t = threadIdx.x;
    const int n0 = blockIdx.x * 16;
    for (int i = t; i < NHIDC * LATENTC; i += 256) Wg2s[i] = Wg2[i];
#pragma unroll
    for (int i = 0; i < 2; i++) {
        int idx = t + i * 256;
        int n = idx >> 5; int c = idx & 31;
        h1s[n][c] = fmaxf(g_AGG1[(n0 + n) * NHIDC + c] + bg1[c], 0.f);
    }
    __syncthreads();
    const int n = t >> 4, j = t & 15;
    float s = 0.f;
#pragma unroll
    for (int i = 0; i < NHIDC; i++) s += h1s[n][i] * Wg2s[i * LATENTC + j];
    g_XW2[(n0 + n) * LATENTC + j] = s;
}

__global__ void __launch_bounds__(256) k_agg2(
    const int* __restrict__ src, const int* __restrict__ dst, const float* __restrict__ w)
{
    int gid = blockIdx.x * 256 + threadIdx.x;
    int e = gid >> 2;
    if (e >= N_EDGESC) return;
    int c = (gid & 3) * 4;
    int s  = __ldg(&src[e]);
    int d  = __ldg(&dst[e]);
    float wt = __ldg(&w[e]);
    float4 v = *(const float4*)&g_XW2[s * LATENTC + c];
    v.x *= wt; v.y *= wt; v.z *= wt; v.w *= wt;
    red_add_v4(&g_AGG2[d * LATENTC + c], v);
}

__global__ void __launch_bounds__(128) k_node(
    const float* __restrict__ bg2, const float* __restrict__ We2,
    const float* __restrict__ be2, const float* __restrict__ Wd1,
    const float* __restrict__ bd1, float* __restrict__ out)
{
    __shared__ float We2s[512], Wd1s[512], be2s[16], bd1s[32], bg2s[16];
    const int t = threadIdx.x;
    for (int i = t; i < 512; i += 128) { We2s[i] = We2[i]; Wd1s[i] = Wd1[i]; }
    if (t < 16) { be2s[t] = be2[t]; bg2s[t] = bg2[t]; }
    if (t < 32) bd1s[t] = bd1[t];
    __syncthreads();

    const int n = blockIdx.x * 128 + t;
    float he[32];
#pragma unroll
    for (int i = 0; i < 8; i++) {
        float4 v = *(const float4*)&g_HE[n * NHIDC + i * 4];
        he[i * 4 + 0] = v.x; he[i * 4 + 1] = v.y; he[i * 4 + 2] = v.z; he[i * 4 + 3] = v.w;
    }
    float zx[16];
#pragma unroll
    for (int j = 0; j < 16; j++) {
        float s = be2s[j];
#pragma unroll
        for (int i = 0; i < 32; i++) s += he[i] * We2s[i * 16 + j];
        zx[j] = fmaxf(s, 0.f);
    }
    float* zo = out + Z_OFF + (size_t)n * 32;
#pragma unroll
    for (int j = 0; j < 16; j++) {
        float za = fmaxf(g_AGG2[n * LATENTC + j] + bg2s[j], 0.f);
        zo[j]      = za;
        zo[16 + j] = zx[j];
    }
#pragma unroll
    for (int i = 0; i < 32; i++) {
        float s = bd1s[i];
#pragma unroll
        for (int j = 0; j < 16; j++) s += zx[j] * Wd1s[j * 32 + i];
        g_HD[n * NHIDC + i] = fmaxf(s, 0.f);
    }
}

__global__ void __launch_bounds__(256) k_feat(
    const float* __restrict__ Wd2, const float* __restrict__ bd2, float* __restrict__ out)
{
    __shared__ float2 hds2[16][32];
    const int t = threadIdx.x;
    const int nb = blockIdx.x * 16;
#pragma unroll
    for (int i = 0; i < 2; i++) {
        int idx = t + i * 256;
        int n = idx >> 5; int c = idx & 31;
        float v = g_HD[(nb + n) * NHIDC + c];
        hds2[n][c] = make_float2(v, v);
    }
    __syncthreads();

    const int c  = t & 127;
    const int ng = (t >> 7) * 8;
    unsigned long long accA[8], accB[8];
#pragma unroll
    for (int nn = 0; nn < 8; nn++) { accA[nn] = 0ull; accB[nn] = 0ull; }

#pragma unroll
    for (int k = 0; k < 32; k++) {
        float4 wv = __ldg((const float4*)&Wd2[k * D_FEATC + c * 4]);
        unsigned long long w01 = pack2(wv.x, wv.y);
        unsigned long long w23 = pack2(wv.z, wv.w);
#pragma unroll
        for (int nn = 0; nn < 8; nn++) {
            unsigned long long h2 = *(const unsigned long long*)&hds2[ng + nn][k];
            ffma2(accA[nn], h2, w01);
            ffma2(accB[nn], h2, w23);
        }
    }
    float4 b = __ldg((const float4*)&bd2[c * 4]);
#pragma unroll
    for (int nn = 0; nn < 8; nn++) {
        float2 vA = unpack2(accA[nn]);
        float2 vB = unpack2(accB[nn]);
        float4 o;
        o.x = fmaxf(vA.x + b.x, 0.f);
        o.y = fmaxf(vA.y + b.y, 0.f);
        o.z = fmaxf(vB.x + b.z, 0.f);
        o.w = fmaxf(vB.y + b.w, 0.f);
        *(float4*)&out[FEAT_OFF + (size_t)(nb + ng + nn) * D_FEATC + c * 4] = o;
    }
}

// ---------------- warp-MMA adjacency (compact [Hi|Lo] smem, 6 CTAs/SM) ----------------
#define AW 72
#define ADJ_SMEM (2 * 128 * AW * 2)      // 36864 bytes

__global__ void __launch_bounds__(256) k_adj_wm(
    const float* __restrict__ zmat, float* __restrict__ out)
{
    extern __shared__ __nv_bfloat16 sm[];
    __nv_bfloat16* Asm = sm;                 // [128][AW]
    __nv_bfloat16* Bsm = sm + 128 * AW;      // [128][AW]

    const int t = threadIdx.x;
    const int wid = t >> 5;
    const int lane = t & 31;

    // triangular tile-pair decode
    const int T = 64;
    const int b = blockIdx.x;
    float disc = 129.0f * 129.0f - 8.0f * (float)b;
    int it = (int)((129.0f - sqrtf(disc)) * 0.5f);
    while (it > 0 && b < it * T - (it * (it - 1)) / 2) it--;
    while (b >= (it + 1) * T - ((it + 1) * it) / 2) it++;
    const int jt = it + (b - (it * T - (it * (it - 1)) / 2));

    // prologue: load z rows, bf16 hi/lo split, compact [Hi|Lo] layout (both tiles)
    for (int idx = t; idx < 2048; idx += 256) {
        int half = idx >> 10;
        int rem  = idx & 1023;
        int row  = rem >> 3;
        int q    = rem & 7;
        int tl   = half ? jt : it;
        float4 v = *(const float4*)&zmat[((size_t)tl * 128 + row) * 32 + q * 4];

        __nv_bfloat16 h0 = __float2bfloat16(v.x);
        __nv_bfloat16 h1 = __float2bfloat16(v.y);
        __nv_bfloat16 h2 = __float2bfloat16(v.z);
        __nv_bfloat16 h3 = __float2bfloat16(v.w);
        __nv_bfloat16 l0 = __float2bfloat16(v.x - __bfloat162float(h0));
        __nv_bfloat16 l1 = __float2bfloat16(v.y - __bfloat162float(h1));
        __nv_bfloat16 l2 = __float2bfloat16(v.z - __bfloat162float(h2));
        __nv_bfloat16 l3 = __float2bfloat16(v.w - __bfloat162float(h3));

        __nv_bfloat162 hp0 = __nv_bfloat162(h0, h1), hp1 = __nv_bfloat162(h2, h3);
        __nv_bfloat162 lp0 = __nv_bfloat162(l0, l1), lp1 = __nv_bfloat162(l2, l3);
        uint2 hw = make_uint2(*(uint32_t*)&hp0, *(uint32_t*)&hp1);
        uint2 lw = make_uint2(*(uint32_t*)&lp0, *(uint32_t*)&lp1);

        __nv_bfloat16* base = (half ? Bsm : Asm) + row * AW + q * 4;
        *(uint2*)(base + 0)  = hw;            // Hi @ [0,32)
        *(uint2*)(base + 32) = lw;            // Lo @ [32,64)
    }
    __syncthreads();

    const int wm = wid & 3;
    const int wn = wid >> 2;
    const int rowW = wm * 32;
    const int colW = wn * 64;

    float c[2][8][4];
#pragma unroll
    for (int mi = 0; mi < 2; mi++)
#pragma unroll
        for (int ni = 0; ni < 8; ni++)
#pragma unroll
            for (int r = 0; r < 4; r++) c[mi][ni][r] = 0.f;

    const uint32_t aBase = smem_u32(Asm);
    const uint32_t bBase = smem_u32(Bsm);
    const int la_r = lane & 15;
    const int la_c = (lane >> 4) * 8;
    const int lb_r = (lane & 7) + ((lane >> 4) * 8);
    const int lb_c = ((lane >> 3) & 1) * 8;

    const int aOffs[6] = {0, 16, 0, 16, 32, 48};
    const int bOffs[6] = {0, 16, 32, 48, 0, 16};

#pragma unroll
    for (int kc = 0; kc < 6; kc++) {
        const int ka = aOffs[kc];
        const int kb = bOffs[kc];
        uint32_t a[2][4];
#pragma unroll
        for (int mi = 0; mi < 2; mi++) {
            uint32_t addr = aBase + ((rowW + mi * 16 + la_r) * AW + ka + la_c) * 2;
            ldsm_x4(a[mi][0], a[mi][1], a[mi][2], a[mi][3], addr);
        }
        uint32_t bfr[8][2];
#pragma unroll
        for (int nb2 = 0; nb2 < 4; nb2++) {
            uint32_t addr = bBase + ((colW + nb2 * 16 + lb_r) * AW + kb + lb_c) * 2;
            uint32_t t0, t1, t2, t3;
            ldsm_x4(t0, t1, t2, t3, addr);
            bfr[nb2 * 2 + 0][0] = t0; bfr[nb2 * 2 + 0][1] = t1;
            bfr[nb2 * 2 + 1][0] = t2; bfr[nb2 * 2 + 1][1] = t3;
        }
#pragma unroll
        for (int mi = 0; mi < 2; mi++)
#pragma unroll
            for (int ni = 0; ni < 8; ni++)
                mma_16816(c[mi][ni], a[mi], bfr[ni]);
    }

    // epilogue: sigmoid + direct fragment stores (R6 form)
    const int rThr = lane >> 2;
    const int cThr = (lane & 3) * 2;
    const size_t gi0 = (size_t)it * 128;
    const size_t gj0 = (size_t)jt * 128;

#pragma unroll
    for (int mi = 0; mi < 2; mi++) {
#pragma unroll
        for (int ni = 0; ni < 8; ni++) {
            float s0 = sigf(c[mi][ni][0]);
            float s1 = sigf(c[mi][ni][1]);
            float s2 = sigf(c[mi][ni][2]);
            float s3 = sigf(c[mi][ni][3]);
            int r0 = rowW + mi * 16 + rThr;
            int cc = colW + ni * 8 + cThr;
            *(float2*)&out[(gi0 + r0)     * (size_t)N_NODESC + gj0 + cc] = make_float2(s0, s1);
            *(float2*)&out[(gi0 + r0 + 8) * (size_t)N_NODESC + gj0 + cc] = make_float2(s2, s3);
            if (it != jt) {
                out[(gj0 + cc)     * (size_t)N_NODESC + gi0 + r0]     = s0;
                out[(gj0 + cc + 1) * (size_t)N_NODESC + gi0 + r0]     = s1;
                out[(gj0 + cc)     * (size_t)N_NODESC + gi0 + r0 + 8] = s2;
                out[(gj0 + cc + 1) * (size_t)N_NODESC + gi0 + r0 + 8] = s3;
            }
        }
    }
}

// ---------------- launch ----------------
extern "C" void kernel_launch(void* const* d_in, const int* in_sizes, int n_in,
                              void* d_out, int out_size)
{
    const float* X   = (const float*)d_in[0];
    const int*   esrc= (const int*)  d_in[1];
    const int*   edst= (const int*)  d_in[2];
    const float* ew  = (const float*)d_in[3];
    const float* Wg1 = (const float*)d_in[4];
    const float* bg1 = (const float*)d_in[5];
    const float* Wg2 = (const float*)d_in[6];
    const float* bg2 = (const float*)d_in[7];
    const float* We1 = (const float*)d_in[8];
    const float* be1 = (const float*)d_in[9];
    const float* We2 = (const float*)d_in[10];
    const float* be2 = (const float*)d_in[11];
    const float* Wd1 = (const float*)d_in[12];
    const float* bd1 = (const float*)d_in[13];
    const float* Wd2 = (const float*)d_in[14];
    const float* bd2 = (const float*)d_in[15];
    float* out = (float*)d_out;

    static int initDone = 0;
    static cudaStream_t s2;
    static cudaEvent_t evFork, evJoin;
    if (!initDone) {
        cudaFuncSetAttribute(k_adj_wm, cudaFuncAttributeMaxDynamicSharedMemorySize, ADJ_SMEM);
        cudaStreamCreateWithFlags(&s2, cudaStreamNonBlocking);
        cudaEventCreateWithFlags(&evFork, cudaEventDisableTiming);
        cudaEventCreateWithFlags(&evJoin, cudaEventDisableTiming);
        initDone = 1;
    }

    k_transform1<<<128, 256>>>(X, Wg1, We1, be1);
    k_agg1      <<<8192, 256>>>(esrc, edst, ew);
    k_layer2pre <<<512, 256>>>(bg1, Wg2);
    k_agg2      <<<4096, 256>>>(esrc, edst, ew);
    k_node      <<<64, 128>>>(bg2, We2, be2, Wd1, bd1, out);

    // fork: k_feat (needs only g_HD) runs concurrently with k_adj (needs only z)
    cudaEventRecord(evFork, 0);
    cudaStreamWaitEvent(s2, evFork, 0);
    k_feat      <<<512, 256, 0, s2>>>(Wd2, bd2, out);
    cudaEventRecord(evJoin, s2);

    k_adj_wm    <<<2080, 256, ADJ_SMEM>>>(out + Z_OFF, out);

    // join: subsequent work (and capture end) depends on both branches
    cudaStreamWaitEvent(0, evJoin, 0);
}